// round 2
// baseline (speedup 1.0000x reference)
#include <cuda_runtime.h>
#include <math.h>

#define N_NODES  20000
#define N_FEAT   128
#define HEADS    56
#define OUTD     32
#define D1       1792      // HEADS*OUTD
#define N_EDGES  100000
#define E_TOT    120000    // + self loops
#define N_GRAPHS 50
#define N_CLASS  2
#define EPS_BN   1e-5f

// ---------------- scratch (static device memory; no allocations) ------------
__device__ float g_bufA[(size_t)N_NODES * D1];   // 143 MB
__device__ float g_bufB[(size_t)N_NODES * D1];   // 143 MB
__device__ float g_as[N_NODES * HEADS];
__device__ float g_ad[N_NODES * HEADS];
__device__ float g_m [N_NODES * HEADS];
__device__ float g_den[N_NODES * HEADS];
__device__ float g_ex[(size_t)E_TOT * HEADS];    // 27 MB
__device__ float g_pool[N_GRAPHS * OUTD];
__device__ float g_cnt[N_GRAPHS];

// ---------------- helpers ---------------------------------------------------
__device__ __forceinline__ void atomicMaxF(float* addr, float val) {
    if (val >= 0.0f) atomicMax((int*)addr, __float_as_int(val));
    else             atomicMin((unsigned int*)addr, __float_as_uint(val));
}

__device__ __forceinline__ void redAddV4(float* addr, float a, float b, float c, float d) {
    asm volatile("red.global.add.v4.f32 [%0], {%1, %2, %3, %4};"
                 :: "l"(addr), "f"(a), "f"(b), "f"(c), "f"(d) : "memory");
}

__global__ void fill_kernel(float* p, float v, int n) {
    int i = blockIdx.x * blockDim.x + threadIdx.x;
    if (i < n) p[i] = v;
}

// ---------------- SGEMM: C[M,N] = A[M,K] @ B[K,N] ---------------------------
// 128x128 block tile, 8x8 thread tile, BK=8, 256 threads. N%128==0, K%8==0.
#define BM 128
#define BN 128
#define BK 8
__global__ __launch_bounds__(256) void sgemm(const float* __restrict__ A,
                                             const float* __restrict__ B,
                                             float* __restrict__ C,
                                             int M, int N, int K) {
    __shared__ float As[BK][BM];
    __shared__ float Bs[BK][BN];
    const int tid = threadIdx.x;
    const int tx = tid % 16;        // N-dir
    const int ty = tid / 16;        // M-dir
    const int rowBase = blockIdx.y * BM;
    const int colBase = blockIdx.x * BN;

    const int aRow  = tid >> 1;          // 0..127
    const int aCol4 = (tid & 1) * 4;     // 0 or 4
    const int bRow  = tid >> 5;          // 0..7
    const int bCol4 = (tid & 31) * 4;

    float acc[8][8];
    #pragma unroll
    for (int i = 0; i < 8; i++)
        #pragma unroll
        for (int j = 0; j < 8; j++) acc[i][j] = 0.0f;

    for (int k0 = 0; k0 < K; k0 += BK) {
        int gr = rowBase + aRow;
        float4 av = (gr < M) ? *(const float4*)&A[(size_t)gr * K + k0 + aCol4]
                             : make_float4(0.f, 0.f, 0.f, 0.f);
        As[aCol4 + 0][aRow] = av.x;
        As[aCol4 + 1][aRow] = av.y;
        As[aCol4 + 2][aRow] = av.z;
        As[aCol4 + 3][aRow] = av.w;
        float4 bv = *(const float4*)&B[(size_t)(k0 + bRow) * N + colBase + bCol4];
        *(float4*)&Bs[bRow][bCol4] = bv;
        __syncthreads();

        #pragma unroll
        for (int k = 0; k < BK; k++) {
            float ar[8], br[8];
            #pragma unroll
            for (int i = 0; i < 8; i++) ar[i] = As[k][ty * 8 + i];
            #pragma unroll
            for (int j = 0; j < 8; j++) br[j] = Bs[k][tx * 8 + j];
            #pragma unroll
            for (int i = 0; i < 8; i++)
                #pragma unroll
                for (int j = 0; j < 8; j++)
                    acc[i][j] = fmaf(ar[i], br[j], acc[i][j]);
        }
        __syncthreads();
    }

    #pragma unroll
    for (int i = 0; i < 8; i++) {
        int gr = rowBase + ty * 8 + i;
        if (gr >= M) continue;
        float* crow = &C[(size_t)gr * N + colBase + tx * 8];
        *(float4*)&crow[0] = make_float4(acc[i][0], acc[i][1], acc[i][2], acc[i][3]);
        *(float4*)&crow[4] = make_float4(acc[i][4], acc[i][5], acc[i][6], acc[i][7]);
    }
}

// ---------------- attention scores a_s/a_d ----------------------------------
// one warp per node; per head: 32-lane dot with att vectors.
__global__ void attn_scores(const float* __restrict__ h,
                            const float* __restrict__ att_s,
                            const float* __restrict__ att_d) {
    int n = blockIdx.x * (blockDim.x / 32) + (threadIdx.x >> 5);
    int lane = threadIdx.x & 31;
    if (n >= N_NODES) return;
    const float* hrow = h + (size_t)n * D1;
    for (int hd = 0; hd < HEADS; hd++) {
        float v = hrow[hd * 32 + lane];
        float s = v * att_s[hd * 32 + lane];
        float d = v * att_d[hd * 32 + lane];
        #pragma unroll
        for (int o = 16; o; o >>= 1) {
            s += __shfl_down_sync(0xffffffffu, s, o);
            d += __shfl_down_sync(0xffffffffu, d, o);
        }
        if (lane == 0) {
            g_as[n * HEADS + hd] = s;
            g_ad[n * HEADS + hd] = d;
        }
    }
}

// ---------------- edge softmax: pass 1 (segment max) ------------------------
__global__ void edge_max(const int* __restrict__ ei) {
    int i = blockIdx.x * blockDim.x + threadIdx.x;
    if (i >= E_TOT * HEADS) return;
    int e = i / HEADS, hd = i - e * HEADS;
    int s, d;
    if (e < N_EDGES) { s = ei[e]; d = ei[N_EDGES + e]; }
    else             { s = d = e - N_EDGES; }
    float x = g_as[s * HEADS + hd] + g_ad[d * HEADS + hd];
    x = (x > 0.0f) ? x : 0.2f * x;   // leaky_relu 0.2
    atomicMaxF(&g_m[d * HEADS + hd], x);
}

// ---------------- edge softmax: pass 2 (exp + segment sum) ------------------
__global__ void edge_exp(const int* __restrict__ ei) {
    int i = blockIdx.x * blockDim.x + threadIdx.x;
    if (i >= E_TOT * HEADS) return;
    int e = i / HEADS, hd = i - e * HEADS;
    int s, d;
    if (e < N_EDGES) { s = ei[e]; d = ei[N_EDGES + e]; }
    else             { s = d = e - N_EDGES; }
    float x = g_as[s * HEADS + hd] + g_ad[d * HEADS + hd];
    x = (x > 0.0f) ? x : 0.2f * x;
    float ex = expf(x - g_m[d * HEADS + hd]);
    g_ex[(size_t)e * HEADS + hd] = ex;
    atomicAdd(&g_den[d * HEADS + hd], ex);
}

// ---------------- message aggregation: out[dst] += alpha * h[src] -----------
// one block (128 threads) per edge; alpha staged in shared; v4 reductions.
__global__ __launch_bounds__(128) void aggregate(const int* __restrict__ ei,
                                                 const float* __restrict__ h,
                                                 float* __restrict__ out) {
    int e = blockIdx.x;
    __shared__ float alpha[HEADS];
    int s, d;
    if (e < N_EDGES) { s = ei[e]; d = ei[N_EDGES + e]; }
    else             { s = d = e - N_EDGES; }
    int t = threadIdx.x;
    if (t < HEADS) alpha[t] = g_ex[(size_t)e * HEADS + t] / g_den[d * HEADS + t];
    __syncthreads();
    const float* hs = h + (size_t)s * D1;
    float* od = out + (size_t)d * D1;
    #pragma unroll
    for (int idx = t * 4; idx < D1; idx += 128 * 4) {
        float a = alpha[idx >> 5];
        float4 v = *(const float4*)&hs[idx];
        redAddV4(&od[idx], a * v.x, a * v.y, a * v.z, a * v.w);
    }
}

// ---------------- bias + ELU + BN1 (elementwise, float4) --------------------
__global__ void elu_bn1(const float* __restrict__ in, float* __restrict__ out,
                        const float* __restrict__ b,  const float* __restrict__ g,
                        const float* __restrict__ bt, const float* __restrict__ mu,
                        const float* __restrict__ var) {
    int i4 = blockIdx.x * blockDim.x + threadIdx.x;
    if (i4 >= N_NODES * D1 / 4) return;
    int i = i4 * 4;
    int c = i % D1;
    float4 v = *(const float4*)&in[i];
    float r[4] = {v.x, v.y, v.z, v.w};
    #pragma unroll
    for (int j = 0; j < 4; j++) {
        float xx = r[j] + b[c + j];
        xx = (xx > 0.0f) ? xx : (expf(xx) - 1.0f);
        r[j] = (xx - mu[c + j]) * rsqrtf(var[c + j] + EPS_BN) * g[c + j] + bt[c + j];
    }
    *(float4*)&out[i] = make_float4(r[0], r[1], r[2], r[3]);
}

// ---------------- head mean + bias + BN2 + pooling --------------------------
// one warp per node; lane = channel 0..31.
__global__ void mean_bn2_pool(const float* __restrict__ out2,
                              const int* __restrict__ batch,
                              const float* __restrict__ b2,
                              const float* __restrict__ g2,
                              const float* __restrict__ bt2,
                              const float* __restrict__ mu2,
                              const float* __restrict__ var2) {
    int n = blockIdx.x * (blockDim.x / 32) + (threadIdx.x >> 5);
    int lane = threadIdx.x & 31;
    if (n >= N_NODES) return;
    const float* row = out2 + (size_t)n * D1;
    float s = 0.0f;
    #pragma unroll 8
    for (int hd = 0; hd < HEADS; hd++) s += row[hd * 32 + lane];
    s = s * (1.0f / HEADS) + b2[lane];
    s = (s - mu2[lane]) * rsqrtf(var2[lane] + EPS_BN) * g2[lane] + bt2[lane];
    int gi = batch[n];
    atomicAdd(&g_pool[gi * OUTD + lane], s);
    if (lane == 0) atomicAdd(&g_cnt[gi], 1.0f);
}

// ---------------- final linear ----------------------------------------------
__global__ void final_lin(const float* __restrict__ lin_w,
                          const float* __restrict__ lin_b,
                          float* __restrict__ out) {
    int i = blockIdx.x * blockDim.x + threadIdx.x;
    if (i >= N_GRAPHS * N_CLASS) return;
    int g = i / N_CLASS, c = i - g * N_CLASS;
    float cnt = fmaxf(g_cnt[g], 1.0f);
    float acc = lin_b[c];
    #pragma unroll
    for (int k = 0; k < OUTD; k++)
        acc += (g_pool[g * OUTD + k] / cnt) * lin_w[k * N_CLASS + c];
    out[i] = acc;
}

// ---------------- host orchestration ----------------------------------------
extern "C" void kernel_launch(void* const* d_in, const int* in_sizes, int n_in,
                              void* d_out, int out_size) {
    const float* x        = (const float*)d_in[0];
    const int*   ei       = (const int*)  d_in[1];
    const int*   batch    = (const int*)  d_in[2];
    const float* W1       = (const float*)d_in[3];
    const float* att_src1 = (const float*)d_in[4];
    const float* att_dst1 = (const float*)d_in[5];
    const float* b1       = (const float*)d_in[6];
    const float* bn1_g    = (const float*)d_in[7];
    const float* bn1_b    = (const float*)d_in[8];
    const float* bn1_m    = (const float*)d_in[9];
    const float* bn1_v    = (const float*)d_in[10];
    const float* W2       = (const float*)d_in[11];
    const float* att_src2 = (const float*)d_in[12];
    const float* att_dst2 = (const float*)d_in[13];
    const float* b2       = (const float*)d_in[14];
    const float* bn2_g    = (const float*)d_in[15];
    const float* bn2_b    = (const float*)d_in[16];
    const float* bn2_m    = (const float*)d_in[17];
    const float* bn2_v    = (const float*)d_in[18];
    const float* lin_w    = (const float*)d_in[19];
    const float* lin_b    = (const float*)d_in[20];
    float* out = (float*)d_out;

    float *bufA, *bufB, *m_ptr, *den_ptr, *pool_ptr, *cnt_ptr;
    cudaGetSymbolAddress((void**)&bufA,    g_bufA);
    cudaGetSymbolAddress((void**)&bufB,    g_bufB);
    cudaGetSymbolAddress((void**)&m_ptr,   g_m);
    cudaGetSymbolAddress((void**)&den_ptr, g_den);
    cudaGetSymbolAddress((void**)&pool_ptr,g_pool);
    cudaGetSymbolAddress((void**)&cnt_ptr, g_cnt);

    const int NH  = N_NODES * HEADS;
    const int EH  = E_TOT * HEADS;
    const int ND1 = N_NODES * D1;
    const int NPOOL = N_GRAPHS * OUTD;
    const float NEG_INF = -__builtin_huge_valf();

    dim3 gemmGridA(D1 / BN, (N_NODES + BM - 1) / BM);

    // ===== layer 1 =====
    sgemm<<<gemmGridA, 256>>>(x, W1, bufA, N_NODES, D1, N_FEAT);           // h1
    attn_scores<<<(N_NODES + 7) / 8, 256>>>(bufA, att_src1, att_dst1);
    fill_kernel<<<(NH + 255) / 256, 256>>>(m_ptr, NEG_INF, NH);
    fill_kernel<<<(NH + 255) / 256, 256>>>(den_ptr, 0.0f, NH);
    fill_kernel<<<(ND1 + 255) / 256, 256>>>(bufB, 0.0f, ND1);
    edge_max<<<(EH + 255) / 256, 256>>>(ei);
    edge_exp<<<(EH + 255) / 256, 256>>>(ei);
    aggregate<<<E_TOT, 128>>>(ei, bufA, bufB);                             // out1 in bufB
    elu_bn1<<<(ND1 / 4 + 255) / 256, 256>>>(bufB, bufA, b1, bn1_g, bn1_b, bn1_m, bn1_v); // x2 in bufA

    // ===== layer 2 =====
    sgemm<<<gemmGridA, 256>>>(bufA, W2, bufB, N_NODES, D1, D1);            // h2 in bufB
    attn_scores<<<(N_NODES + 7) / 8, 256>>>(bufB, att_src2, att_dst2);
    fill_kernel<<<(NH + 255) / 256, 256>>>(m_ptr, NEG_INF, NH);
    fill_kernel<<<(NH + 255) / 256, 256>>>(den_ptr, 0.0f, NH);
    fill_kernel<<<(ND1 + 255) / 256, 256>>>(bufA, 0.0f, ND1);
    edge_max<<<(EH + 255) / 256, 256>>>(ei);
    edge_exp<<<(EH + 255) / 256, 256>>>(ei);
    aggregate<<<E_TOT, 128>>>(ei, bufB, bufA);                             // out2 in bufA

    // ===== head-mean + BN2 + pool + linear =====
    fill_kernel<<<(NPOOL + 255) / 256, 256>>>(pool_ptr, 0.0f, NPOOL);
    fill_kernel<<<1, 64>>>(cnt_ptr, 0.0f, N_GRAPHS);
    mean_bn2_pool<<<(N_NODES + 7) / 8, 256>>>(bufA, batch, b2, bn2_g, bn2_b, bn2_m, bn2_v);
    final_lin<<<1, 128>>>(lin_w, lin_b, out);
}

// round 3
// speedup vs baseline: 2.1593x; 2.1593x over previous
#include <cuda_runtime.h>
#include <math.h>
#include <stdint.h>

#define N_NODES  20000
#define N_FEAT   128
#define HEADS    56
#define OUTD     32
#define D1       1792      // HEADS*OUTD
#define N_EDGES  100000
#define E_TOT    120000    // + self loops
#define N_GRAPHS 50
#define N_CLASS  2
#define EPS_BN   1e-5f

// ---------------- scratch (static device memory; no allocations) ------------
__device__ float g_bufA[(size_t)N_NODES * D1];   // 143 MB
__device__ float g_bufB[(size_t)N_NODES * D1];   // 143 MB
__device__ float g_as[N_NODES * HEADS];
__device__ float g_ad[N_NODES * HEADS];
__device__ float g_m [N_NODES * HEADS];
__device__ float g_den[N_NODES * HEADS];
__device__ float g_ex[(size_t)E_TOT * HEADS];    // 27 MB
__device__ float g_pool[N_GRAPHS * OUTD];
__device__ float g_cnt[N_GRAPHS];

// ---------------- helpers ---------------------------------------------------
__device__ __forceinline__ void atomicMaxF(float* addr, float val) {
    if (val >= 0.0f) atomicMax((int*)addr, __float_as_int(val));
    else             atomicMin((unsigned int*)addr, __float_as_uint(val));
}

__device__ __forceinline__ void redAddV4(float* addr, float a, float b, float c, float d) {
    asm volatile("red.global.add.v4.f32 [%0], {%1, %2, %3, %4};"
                 :: "l"(addr), "f"(a), "f"(b), "f"(c), "f"(d) : "memory");
}

__device__ __forceinline__ uint32_t f2tf32(float f) {
    uint32_t u;
    asm("cvt.rna.tf32.f32 %0, %1;" : "=r"(u) : "f"(f));
    return u;
}

__device__ __forceinline__ void cpAsync16(uint32_t smem_addr, const void* gptr, int src_bytes) {
    asm volatile("cp.async.ca.shared.global [%0], [%1], 16, %2;"
                 :: "r"(smem_addr), "l"(gptr), "r"(src_bytes));
}
__device__ __forceinline__ void cpCommit() { asm volatile("cp.async.commit_group;"); }
template <int N>
__device__ __forceinline__ void cpWait() { asm volatile("cp.async.wait_group %0;" :: "n"(N)); }

__global__ void fill_kernel(float* p, float v, int n) {
    int i = blockIdx.x * blockDim.x + threadIdx.x;
    if (i < n) p[i] = v;
}

// ---------------- TF32 tensor-core GEMM: C[M,N] = A[M,K] @ B[K,N] ------------
// 128x128 block tile, BK=32, 8 warps (2x4), 64x32 warp tile, mma.m16n8k8.tf32.
// A smem: [128][36] row-major (pad 36 => bank 4g+t, conflict-free frags)
// B smem: [32][132]  row-major (pad 132 => bank 4t+g, conflict-free frags)
#define GBM 128
#define GBN 128
#define GBK 32
#define AS_STRIDE 36
#define BS_STRIDE 132
#define A_FLOATS (GBM * AS_STRIDE)          // 4608
#define B_FLOATS (GBK * BS_STRIDE)          // 4224
#define STAGE_FLOATS (A_FLOATS + B_FLOATS)  // 8832

__global__ __launch_bounds__(256, 2) void tf32_gemm(const float* __restrict__ A,
                                                    const float* __restrict__ B,
                                                    float* __restrict__ C,
                                                    int M, int N, int K) {
    extern __shared__ float smem[];
    const int tid   = threadIdx.x;
    const int wid   = tid >> 5;
    const int lane  = tid & 31;
    const int g     = lane >> 2;   // group id (0..7)
    const int t     = lane & 3;    // thread-in-group (0..3)
    const int warpM = wid & 1;     // 0..1
    const int warpN = wid >> 1;    // 0..3
    const int rowBase = blockIdx.y * GBM;
    const int colBase = blockIdx.x * GBN;

    float acc[4][4][4];
    #pragma unroll
    for (int i = 0; i < 4; i++)
        #pragma unroll
        for (int j = 0; j < 4; j++)
            #pragma unroll
            for (int k = 0; k < 4; k++) acc[i][j][k] = 0.0f;

    uint32_t smemBase;
    {
        uint32_t sb = (uint32_t)__cvta_generic_to_shared(smem);
        smemBase = sb;
    }

    const int T = K / GBK;

    // ---- tile loader (cp.async) ----
    auto load_tiles = [&](int k0, int stage) {
        uint32_t sA = smemBase + stage * STAGE_FLOATS * 4;
        uint32_t sB = sA + A_FLOATS * 4;
        #pragma unroll
        for (int j = 0; j < 4; j++) {
            int idx = tid + j * 256;          // 0..1023
            int m   = idx >> 3;               // 0..127
            int k4  = (idx & 7) * 4;          // 0..28
            int gr  = rowBase + m;
            const float* src = A + (size_t)gr * K + k0 + k4;
            cpAsync16(sA + (m * AS_STRIDE + k4) * 4, src, (gr < M) ? 16 : 0);
        }
        #pragma unroll
        for (int j = 0; j < 4; j++) {
            int idx = tid + j * 256;
            int kk  = idx >> 5;               // 0..31
            int n4  = (idx & 31) * 4;         // 0..124
            const float* src = B + (size_t)(k0 + kk) * N + colBase + n4;
            cpAsync16(sB + (kk * BS_STRIDE + n4) * 4, src, 16);
        }
    };

    load_tiles(0, 0);
    cpCommit();

    for (int it = 0; it < T; ++it) {
        if (it + 1 < T) {
            load_tiles((it + 1) * GBK, (it + 1) & 1);
            cpCommit();
            cpWait<1>();
        } else {
            cpWait<0>();
        }
        __syncthreads();

        const float* As_s = smem + (it & 1) * STAGE_FLOATS;
        const float* Bs_s = As_s + A_FLOATS;

        #pragma unroll
        for (int ks = 0; ks < 4; ks++) {
            uint32_t af[4][4], bf[4][2];
            #pragma unroll
            for (int mt = 0; mt < 4; mt++) {
                int r = warpM * 64 + mt * 16 + g;
                const float* p0 = &As_s[r * AS_STRIDE + ks * 8 + t];
                af[mt][0] = f2tf32(p0[0]);
                af[mt][1] = f2tf32(p0[8 * AS_STRIDE]);
                af[mt][2] = f2tf32(p0[4]);
                af[mt][3] = f2tf32(p0[8 * AS_STRIDE + 4]);
            }
            #pragma unroll
            for (int nt = 0; nt < 4; nt++) {
                int c = warpN * 32 + nt * 8 + g;
                const float* p0 = &Bs_s[(ks * 8 + t) * BS_STRIDE + c];
                bf[nt][0] = f2tf32(p0[0]);
                bf[nt][1] = f2tf32(p0[4 * BS_STRIDE]);
            }
            #pragma unroll
            for (int mt = 0; mt < 4; mt++)
                #pragma unroll
                for (int nt = 0; nt < 4; nt++) {
                    float* d = acc[mt][nt];
                    asm volatile(
                        "mma.sync.aligned.m16n8k8.row.col.f32.tf32.tf32.f32 "
                        "{%0,%1,%2,%3}, {%4,%5,%6,%7}, {%8,%9}, {%0,%1,%2,%3};"
                        : "+f"(d[0]), "+f"(d[1]), "+f"(d[2]), "+f"(d[3])
                        : "r"(af[mt][0]), "r"(af[mt][1]), "r"(af[mt][2]), "r"(af[mt][3]),
                          "r"(bf[nt][0]), "r"(bf[nt][1]));
                }
        }
        __syncthreads();
    }

    // ---- epilogue: c0,c1 @ (g, 2t..2t+1); c2,c3 @ (g+8, ...) ----
    #pragma unroll
    for (int mt = 0; mt < 4; mt++) {
        int r0 = rowBase + warpM * 64 + mt * 16 + g;
        #pragma unroll
        for (int nt = 0; nt < 4; nt++) {
            int c = colBase + warpN * 32 + nt * 8 + 2 * t;
            if (r0 < M)
                *(float2*)&C[(size_t)r0 * N + c] = make_float2(acc[mt][nt][0], acc[mt][nt][1]);
            if (r0 + 8 < M)
                *(float2*)&C[(size_t)(r0 + 8) * N + c] = make_float2(acc[mt][nt][2], acc[mt][nt][3]);
        }
    }
}

// ---------------- attention scores a_s/a_d ----------------------------------
__global__ void attn_scores(const float* __restrict__ h,
                            const float* __restrict__ att_s,
                            const float* __restrict__ att_d) {
    int n = blockIdx.x * (blockDim.x / 32) + (threadIdx.x >> 5);
    int lane = threadIdx.x & 31;
    if (n >= N_NODES) return;
    const float* hrow = h + (size_t)n * D1;
    for (int hd = 0; hd < HEADS; hd++) {
        float v = hrow[hd * 32 + lane];
        float s = v * att_s[hd * 32 + lane];
        float d = v * att_d[hd * 32 + lane];
        #pragma unroll
        for (int o = 16; o; o >>= 1) {
            s += __shfl_down_sync(0xffffffffu, s, o);
            d += __shfl_down_sync(0xffffffffu, d, o);
        }
        if (lane == 0) {
            g_as[n * HEADS + hd] = s;
            g_ad[n * HEADS + hd] = d;
        }
    }
}

// ---------------- edge softmax: pass 1 (segment max) ------------------------
__global__ void edge_max(const int* __restrict__ ei) {
    int i = blockIdx.x * blockDim.x + threadIdx.x;
    if (i >= E_TOT * HEADS) return;
    int e = i / HEADS, hd = i - e * HEADS;
    int s, d;
    if (e < N_EDGES) { s = ei[e]; d = ei[N_EDGES + e]; }
    else             { s = d = e - N_EDGES; }
    float x = g_as[s * HEADS + hd] + g_ad[d * HEADS + hd];
    x = (x > 0.0f) ? x : 0.2f * x;   // leaky_relu 0.2
    atomicMaxF(&g_m[d * HEADS + hd], x);
}

// ---------------- edge softmax: pass 2 (exp + segment sum) ------------------
__global__ void edge_exp(const int* __restrict__ ei) {
    int i = blockIdx.x * blockDim.x + threadIdx.x;
    if (i >= E_TOT * HEADS) return;
    int e = i / HEADS, hd = i - e * HEADS;
    int s, d;
    if (e < N_EDGES) { s = ei[e]; d = ei[N_EDGES + e]; }
    else             { s = d = e - N_EDGES; }
    float x = g_as[s * HEADS + hd] + g_ad[d * HEADS + hd];
    x = (x > 0.0f) ? x : 0.2f * x;
    float ex = expf(x - g_m[d * HEADS + hd]);
    g_ex[(size_t)e * HEADS + hd] = ex;
    atomicAdd(&g_den[d * HEADS + hd], ex);
}

// ---------------- message aggregation: out[dst] += alpha * h[src] -----------
__global__ __launch_bounds__(128) void aggregate(const int* __restrict__ ei,
                                                 const float* __restrict__ h,
                                                 float* __restrict__ out) {
    int e = blockIdx.x;
    __shared__ float alpha[HEADS];
    int s, d;
    if (e < N_EDGES) { s = ei[e]; d = ei[N_EDGES + e]; }
    else             { s = d = e - N_EDGES; }
    int t = threadIdx.x;
    if (t < HEADS) alpha[t] = g_ex[(size_t)e * HEADS + t] / g_den[d * HEADS + t];
    __syncthreads();
    const float* hs = h + (size_t)s * D1;
    float* od = out + (size_t)d * D1;
    #pragma unroll
    for (int idx = t * 4; idx < D1; idx += 128 * 4) {
        float a = alpha[idx >> 5];
        float4 v = *(const float4*)&hs[idx];
        redAddV4(&od[idx], a * v.x, a * v.y, a * v.z, a * v.w);
    }
}

// ---------------- bias + ELU + BN1 (elementwise, float4) --------------------
__global__ void elu_bn1(const float* __restrict__ in, float* __restrict__ out,
                        const float* __restrict__ b,  const float* __restrict__ g,
                        const float* __restrict__ bt, const float* __restrict__ mu,
                        const float* __restrict__ var) {
    int i4 = blockIdx.x * blockDim.x + threadIdx.x;
    if (i4 >= N_NODES * D1 / 4) return;
    int i = i4 * 4;
    int c = i % D1;
    float4 v = *(const float4*)&in[i];
    float r[4] = {v.x, v.y, v.z, v.w};
    #pragma unroll
    for (int j = 0; j < 4; j++) {
        float xx = r[j] + b[c + j];
        xx = (xx > 0.0f) ? xx : (expf(xx) - 1.0f);
        r[j] = (xx - mu[c + j]) * rsqrtf(var[c + j] + EPS_BN) * g[c + j] + bt[c + j];
    }
    *(float4*)&out[i] = make_float4(r[0], r[1], r[2], r[3]);
}

// ---------------- head mean + bias + BN2 + pooling --------------------------
__global__ void mean_bn2_pool(const float* __restrict__ out2,
                              const int* __restrict__ batch,
                              const float* __restrict__ b2,
                              const float* __restrict__ g2,
                              const float* __restrict__ bt2,
                              const float* __restrict__ mu2,
                              const float* __restrict__ var2) {
    int n = blockIdx.x * (blockDim.x / 32) + (threadIdx.x >> 5);
    int lane = threadIdx.x & 31;
    if (n >= N_NODES) return;
    const float* row = out2 + (size_t)n * D1;
    float s = 0.0f;
    #pragma unroll 8
    for (int hd = 0; hd < HEADS; hd++) s += row[hd * 32 + lane];
    s = s * (1.0f / HEADS) + b2[lane];
    s = (s - mu2[lane]) * rsqrtf(var2[lane] + EPS_BN) * g2[lane] + bt2[lane];
    int gi = batch[n];
    atomicAdd(&g_pool[gi * OUTD + lane], s);
    if (lane == 0) atomicAdd(&g_cnt[gi], 1.0f);
}

// ---------------- final linear ----------------------------------------------
__global__ void final_lin(const float* __restrict__ lin_w,
                          const float* __restrict__ lin_b,
                          float* __restrict__ out) {
    int i = blockIdx.x * blockDim.x + threadIdx.x;
    if (i >= N_GRAPHS * N_CLASS) return;
    int g = i / N_CLASS, c = i - g * N_CLASS;
    float cnt = fmaxf(g_cnt[g], 1.0f);
    float acc = lin_b[c];
    #pragma unroll
    for (int k = 0; k < OUTD; k++)
        acc += (g_pool[g * OUTD + k] / cnt) * lin_w[k * N_CLASS + c];
    out[i] = acc;
}

// ---------------- host orchestration ----------------------------------------
extern "C" void kernel_launch(void* const* d_in, const int* in_sizes, int n_in,
                              void* d_out, int out_size) {
    const float* x        = (const float*)d_in[0];
    const int*   ei       = (const int*)  d_in[1];
    const int*   batch    = (const int*)  d_in[2];
    const float* W1       = (const float*)d_in[3];
    const float* att_src1 = (const float*)d_in[4];
    const float* att_dst1 = (const float*)d_in[5];
    const float* b1       = (const float*)d_in[6];
    const float* bn1_g    = (const float*)d_in[7];
    const float* bn1_b    = (const float*)d_in[8];
    const float* bn1_m    = (const float*)d_in[9];
    const float* bn1_v    = (const float*)d_in[10];
    const float* W2       = (const float*)d_in[11];
    const float* att_src2 = (const float*)d_in[12];
    const float* att_dst2 = (const float*)d_in[13];
    const float* b2       = (const float*)d_in[14];
    const float* bn2_g    = (const float*)d_in[15];
    const float* bn2_b    = (const float*)d_in[16];
    const float* bn2_m    = (const float*)d_in[17];
    const float* bn2_v    = (const float*)d_in[18];
    const float* lin_w    = (const float*)d_in[19];
    const float* lin_b    = (const float*)d_in[20];
    float* out = (float*)d_out;

    float *bufA, *bufB, *m_ptr, *den_ptr, *pool_ptr, *cnt_ptr;
    cudaGetSymbolAddress((void**)&bufA,    g_bufA);
    cudaGetSymbolAddress((void**)&bufB,    g_bufB);
    cudaGetSymbolAddress((void**)&m_ptr,   g_m);
    cudaGetSymbolAddress((void**)&den_ptr, g_den);
    cudaGetSymbolAddress((void**)&pool_ptr,g_pool);
    cudaGetSymbolAddress((void**)&cnt_ptr, g_cnt);

    const int NH  = N_NODES * HEADS;
    const int EH  = E_TOT * HEADS;
    const int ND1 = N_NODES * D1;
    const int NPOOL = N_GRAPHS * OUTD;
    const float NEG_INF = -__builtin_huge_valf();

    const int SMEM_BYTES = 2 * STAGE_FLOATS * 4;   // 70656 B
    cudaFuncSetAttribute(tf32_gemm, cudaFuncAttributeMaxDynamicSharedMemorySize, SMEM_BYTES);

    dim3 gemmGrid(D1 / GBN, (N_NODES + GBM - 1) / GBM);

    // ===== init fills first (also puts the GEMM at launch idx 5 for ncu) =====
    fill_kernel<<<(NH + 255) / 256, 256>>>(m_ptr, NEG_INF, NH);
    fill_kernel<<<(NH + 255) / 256, 256>>>(den_ptr, 0.0f, NH);
    fill_kernel<<<(ND1 + 255) / 256, 256>>>(bufB, 0.0f, ND1);
    fill_kernel<<<(NPOOL + 255) / 256, 256>>>(pool_ptr, 0.0f, NPOOL);
    fill_kernel<<<1, 64>>>(cnt_ptr, 0.0f, N_GRAPHS);

    // ===== layer 1 =====
    tf32_gemm<<<gemmGrid, 256, SMEM_BYTES>>>(x, W1, bufA, N_NODES, D1, N_FEAT);  // h1
    attn_scores<<<(N_NODES + 7) / 8, 256>>>(bufA, att_src1, att_dst1);
    edge_max<<<(EH + 255) / 256, 256>>>(ei);
    edge_exp<<<(EH + 255) / 256, 256>>>(ei);
    aggregate<<<E_TOT, 128>>>(ei, bufA, bufB);                                   // out1 in bufB
    elu_bn1<<<(ND1 / 4 + 255) / 256, 256>>>(bufB, bufA, b1, bn1_g, bn1_b, bn1_m, bn1_v);

    // ===== layer 2 =====
    tf32_gemm<<<gemmGrid, 256, SMEM_BYTES>>>(bufA, W2, bufB, N_NODES, D1, D1);   // h2 in bufB
    attn_scores<<<(N_NODES + 7) / 8, 256>>>(bufB, att_src2, att_dst2);
    fill_kernel<<<(NH + 255) / 256, 256>>>(m_ptr, NEG_INF, NH);
    fill_kernel<<<(NH + 255) / 256, 256>>>(den_ptr, 0.0f, NH);
    fill_kernel<<<(ND1 + 255) / 256, 256>>>(bufA, 0.0f, ND1);
    edge_max<<<(EH + 255) / 256, 256>>>(ei);
    edge_exp<<<(EH + 255) / 256, 256>>>(ei);
    aggregate<<<E_TOT, 128>>>(ei, bufB, bufA);                                   // out2 in bufA

    // ===== head-mean + BN2 + pool + linear =====
    mean_bn2_pool<<<(N_NODES + 7) / 8, 256>>>(bufA, batch, b2, bn2_g, bn2_b, bn2_m, bn2_v);
    final_lin<<<1, 128>>>(lin_w, lin_b, out);
}

// round 4
// speedup vs baseline: 2.6565x; 1.2303x over previous
#include <cuda_runtime.h>
#include <cuda_bf16.h>
#include <math.h>
#include <stdint.h>

#define N_NODES  20000
#define N_FEAT   128
#define HEADS    56
#define OUTD     32
#define D1       1792      // HEADS*OUTD
#define N_EDGES  100000
#define E_TOT    120000    // + self loops
#define N_GRAPHS 50
#define N_CLASS  2
#define EPS_BN   1e-5f

// ---------------- scratch (static device memory; no allocations) ------------
__device__ float g_bufA[(size_t)N_NODES * D1];   // 143 MB
__device__ float g_bufB[(size_t)N_NODES * D1];   // 143 MB
__device__ __nv_bfloat16 g_actbf[(size_t)N_NODES * D1];  // 71.7 MB (bf16 activations)
__device__ __nv_bfloat16 g_xbf [(size_t)N_NODES * N_FEAT];
__device__ __nv_bfloat16 g_w1t [(size_t)D1 * N_FEAT];    // W1^T [N][K]
__device__ __nv_bfloat16 g_w2t [(size_t)D1 * D1];        // W2^T [N][K]
__device__ float g_as[N_NODES * HEADS];
__device__ float g_ad[N_NODES * HEADS];
__device__ float g_m [N_NODES * HEADS];
__device__ float g_den[N_NODES * HEADS];
__device__ float g_ex[(size_t)E_TOT * HEADS];
__device__ float g_pool[N_GRAPHS * OUTD];
__device__ float g_cnt[N_GRAPHS];

// ---------------- helpers ---------------------------------------------------
__device__ __forceinline__ void atomicMaxF(float* addr, float val) {
    if (val >= 0.0f) atomicMax((int*)addr, __float_as_int(val));
    else             atomicMin((unsigned int*)addr, __float_as_uint(val));
}

__device__ __forceinline__ void redAddV4(float* addr, float a, float b, float c, float d) {
    asm volatile("red.global.add.v4.f32 [%0], {%1, %2, %3, %4};"
                 :: "l"(addr), "f"(a), "f"(b), "f"(c), "f"(d) : "memory");
}

__device__ __forceinline__ void cpAsync16(uint32_t smem_addr, const void* gptr, int src_bytes) {
    asm volatile("cp.async.ca.shared.global [%0], [%1], 16, %2;"
                 :: "r"(smem_addr), "l"(gptr), "r"(src_bytes));
}
__device__ __forceinline__ void cpCommit() { asm volatile("cp.async.commit_group;"); }
template <int N>
__device__ __forceinline__ void cpWait() { asm volatile("cp.async.wait_group %0;" :: "n"(N)); }

__global__ void fill_kernel(float* p, float v, int n) {
    int i = blockIdx.x * blockDim.x + threadIdx.x;
    if (i < n) p[i] = v;
}

// ---------------- f32 -> bf16 elementwise (vector of 4) ---------------------
__global__ void cvt_bf16(const float* __restrict__ in, __nv_bfloat16* __restrict__ out, int n4) {
    int i = blockIdx.x * blockDim.x + threadIdx.x;
    if (i >= n4) return;
    float4 v = ((const float4*)in)[i];
    __nv_bfloat162 lo = __floats2bfloat162_rn(v.x, v.y);
    __nv_bfloat162 hi = __floats2bfloat162_rn(v.z, v.w);
    ((__nv_bfloat162*)out)[2 * i]     = lo;
    ((__nv_bfloat162*)out)[2 * i + 1] = hi;
}

// ---------------- f32 [K][N] -> bf16 [N][K] tiled transpose -----------------
__global__ void transpose_cvt(const float* __restrict__ in, __nv_bfloat16* __restrict__ out,
                              int K, int N) {
    __shared__ float tile[32][33];
    int k0 = blockIdx.y * 32, n0 = blockIdx.x * 32;
    #pragma unroll
    for (int j = 0; j < 4; j++) {
        int kk = threadIdx.y + j * 8;
        tile[kk][threadIdx.x] = in[(size_t)(k0 + kk) * N + n0 + threadIdx.x];
    }
    __syncthreads();
    #pragma unroll
    for (int j = 0; j < 4; j++) {
        int nn = threadIdx.y + j * 8;
        out[(size_t)(n0 + nn) * K + k0 + threadIdx.x] = __float2bfloat16(tile[threadIdx.x][nn]);
    }
}

// ---------------- BF16 tensor-core GEMM: C[M,N] = A[M,K] @ BT[N,K]^T --------
// A: bf16 [M][K] row-major. BT: bf16 [N][K] (i.e. B transposed). C: f32.
// 128x128x32 tiles, 8 warps (2x4), 64x32 warp tiles, mma.m16n8k16, 3 stages.
#define BM 128
#define BN 128
#define BK 32
#define TS 40                       // smem row stride in bf16 (pad 8)
#define A_ELE (BM * TS)             // 5120 bf16
#define STAGE_BYTES (2 * A_ELE * 2) // A + B tiles = 20480 B
#define NSTAGE 3

__global__ __launch_bounds__(256, 2) void bf16_gemm(const __nv_bfloat16* __restrict__ A,
                                                    const __nv_bfloat16* __restrict__ BT,
                                                    float* __restrict__ C,
                                                    int M, int N, int K) {
    extern __shared__ __nv_bfloat16 smem[];
    const int tid   = threadIdx.x;
    const int wid   = tid >> 5;
    const int lane  = tid & 31;
    const int g     = lane >> 2;
    const int t     = lane & 3;
    const int warpM = wid & 1;
    const int warpN = wid >> 1;
    const int rowBase = blockIdx.y * BM;
    const int colBase = blockIdx.x * BN;

    float acc[4][4][4];
    #pragma unroll
    for (int i = 0; i < 4; i++)
        #pragma unroll
        for (int j = 0; j < 4; j++)
            #pragma unroll
            for (int k = 0; k < 4; k++) acc[i][j][k] = 0.0f;

    uint32_t smemBase = (uint32_t)__cvta_generic_to_shared(smem);
    const int T = K / BK;

    auto load_tiles = [&](int it, int stage) {
        int k0 = it * BK;
        uint32_t sA = smemBase + stage * STAGE_BYTES;
        uint32_t sB = sA + A_ELE * 2;
        #pragma unroll
        for (int j = 0; j < 2; j++) {
            int idx = tid + j * 256;          // 0..511
            int m   = idx >> 2;               // 0..127
            int c8  = (idx & 3) * 8;          // 0,8,16,24
            int gr  = rowBase + m;
            const __nv_bfloat16* src = A + (size_t)(gr < M ? gr : 0) * K + k0 + c8;
            cpAsync16(sA + (m * TS + c8) * 2, src, (gr < M) ? 16 : 0);
        }
        #pragma unroll
        for (int j = 0; j < 2; j++) {
            int idx = tid + j * 256;
            int n   = idx >> 2;
            int c8  = (idx & 3) * 8;
            const __nv_bfloat16* src = BT + (size_t)(colBase + n) * K + k0 + c8;
            cpAsync16(sB + (n * TS + c8) * 2, src, 16);
        }
    };

    load_tiles(0, 0);
    cpCommit();
    if (T > 1) load_tiles(1, 1);
    cpCommit();

    for (int it = 0; it < T; ++it) {
        cpWait<1>();
        __syncthreads();
        if (it + 2 < T) load_tiles(it + 2, (it + 2) % NSTAGE);
        cpCommit();

        const __nv_bfloat16* As_s = smem + (it % NSTAGE) * (STAGE_BYTES / 2);
        const __nv_bfloat16* Bs_s = As_s + A_ELE;

        #pragma unroll
        for (int ks = 0; ks < 2; ks++) {
            uint32_t af[4][4], bf[4][2];
            #pragma unroll
            for (int mt = 0; mt < 4; mt++) {
                int r = warpM * 64 + mt * 16 + g;
                const __nv_bfloat16* p = &As_s[r * TS + ks * 16 + 2 * t];
                af[mt][0] = *(const uint32_t*)&p[0];
                af[mt][1] = *(const uint32_t*)&p[8 * TS];
                af[mt][2] = *(const uint32_t*)&p[8];
                af[mt][3] = *(const uint32_t*)&p[8 * TS + 8];
            }
            #pragma unroll
            for (int nt = 0; nt < 4; nt++) {
                int c = warpN * 32 + nt * 8 + g;
                const __nv_bfloat16* p = &Bs_s[c * TS + ks * 16 + 2 * t];
                bf[nt][0] = *(const uint32_t*)&p[0];
                bf[nt][1] = *(const uint32_t*)&p[8];
            }
            #pragma unroll
            for (int mt = 0; mt < 4; mt++)
                #pragma unroll
                for (int nt = 0; nt < 4; nt++) {
                    float* d = acc[mt][nt];
                    asm volatile(
                        "mma.sync.aligned.m16n8k16.row.col.f32.bf16.bf16.f32 "
                        "{%0,%1,%2,%3}, {%4,%5,%6,%7}, {%8,%9}, {%0,%1,%2,%3};"
                        : "+f"(d[0]), "+f"(d[1]), "+f"(d[2]), "+f"(d[3])
                        : "r"(af[mt][0]), "r"(af[mt][1]), "r"(af[mt][2]), "r"(af[mt][3]),
                          "r"(bf[nt][0]), "r"(bf[nt][1]));
                }
        }
        __syncthreads();
    }

    #pragma unroll
    for (int mt = 0; mt < 4; mt++) {
        int r0 = rowBase + warpM * 64 + mt * 16 + g;
        #pragma unroll
        for (int nt = 0; nt < 4; nt++) {
            int c = colBase + warpN * 32 + nt * 8 + 2 * t;
            if (r0 < M)
                *(float2*)&C[(size_t)r0 * N + c] = make_float2(acc[mt][nt][0], acc[mt][nt][1]);
            if (r0 + 8 < M)
                *(float2*)&C[(size_t)(r0 + 8) * N + c] = make_float2(acc[mt][nt][2], acc[mt][nt][3]);
        }
    }
}

// ---------------- attention scores a_s/a_d ----------------------------------
__global__ void attn_scores(const float* __restrict__ h,
                            const float* __restrict__ att_s,
                            const float* __restrict__ att_d) {
    int n = blockIdx.x * (blockDim.x / 32) + (threadIdx.x >> 5);
    int lane = threadIdx.x & 31;
    if (n >= N_NODES) return;
    const float* hrow = h + (size_t)n * D1;
    for (int hd = 0; hd < HEADS; hd++) {
        float v = hrow[hd * 32 + lane];
        float s = v * att_s[hd * 32 + lane];
        float d = v * att_d[hd * 32 + lane];
        #pragma unroll
        for (int o = 16; o; o >>= 1) {
            s += __shfl_down_sync(0xffffffffu, s, o);
            d += __shfl_down_sync(0xffffffffu, d, o);
        }
        if (lane == 0) {
            g_as[n * HEADS + hd] = s;
            g_ad[n * HEADS + hd] = d;
        }
    }
}

// ---------------- edge softmax: pass 1 (segment max) ------------------------
__global__ void edge_max(const int* __restrict__ ei) {
    int i = blockIdx.x * blockDim.x + threadIdx.x;
    if (i >= E_TOT * HEADS) return;
    int e = i / HEADS, hd = i - e * HEADS;
    int s, d;
    if (e < N_EDGES) { s = ei[e]; d = ei[N_EDGES + e]; }
    else             { s = d = e - N_EDGES; }
    float x = g_as[s * HEADS + hd] + g_ad[d * HEADS + hd];
    x = (x > 0.0f) ? x : 0.2f * x;
    atomicMaxF(&g_m[d * HEADS + hd], x);
}

// ---------------- edge softmax: pass 2 (exp + segment sum) ------------------
__global__ void edge_exp(const int* __restrict__ ei) {
    int i = blockIdx.x * blockDim.x + threadIdx.x;
    if (i >= E_TOT * HEADS) return;
    int e = i / HEADS, hd = i - e * HEADS;
    int s, d;
    if (e < N_EDGES) { s = ei[e]; d = ei[N_EDGES + e]; }
    else             { s = d = e - N_EDGES; }
    float x = g_as[s * HEADS + hd] + g_ad[d * HEADS + hd];
    x = (x > 0.0f) ? x : 0.2f * x;
    float ex = expf(x - g_m[d * HEADS + hd]);
    g_ex[(size_t)e * HEADS + hd] = ex;
    atomicAdd(&g_den[d * HEADS + hd], ex);
}

// ---------------- message aggregation: out[dst] += alpha * h[src] -----------
__global__ __launch_bounds__(128) void aggregate(const int* __restrict__ ei,
                                                 const float* __restrict__ h,
                                                 float* __restrict__ out) {
    int e = blockIdx.x;
    __shared__ float alpha[HEADS];
    int s, d;
    if (e < N_EDGES) { s = ei[e]; d = ei[N_EDGES + e]; }
    else             { s = d = e - N_EDGES; }
    int t = threadIdx.x;
    if (t < HEADS) alpha[t] = g_ex[(size_t)e * HEADS + t] / g_den[d * HEADS + t];
    __syncthreads();
    const float* hs = h + (size_t)s * D1;
    float* od = out + (size_t)d * D1;
    #pragma unroll
    for (int idx = t * 4; idx < D1; idx += 128 * 4) {
        float a = alpha[idx >> 5];
        float4 v = *(const float4*)&hs[idx];
        redAddV4(&od[idx], a * v.x, a * v.y, a * v.z, a * v.w);
    }
}

// ---------------- bias + ELU + BN1 -> bf16 output ---------------------------
__global__ void elu_bn1(const float* __restrict__ in, __nv_bfloat16* __restrict__ out,
                        const float* __restrict__ b,  const float* __restrict__ g,
                        const float* __restrict__ bt, const float* __restrict__ mu,
                        const float* __restrict__ var) {
    int i4 = blockIdx.x * blockDim.x + threadIdx.x;
    if (i4 >= N_NODES * D1 / 4) return;
    int i = i4 * 4;
    int c = i % D1;
    float4 v = *(const float4*)&in[i];
    float r[4] = {v.x, v.y, v.z, v.w};
    #pragma unroll
    for (int j = 0; j < 4; j++) {
        float xx = r[j] + b[c + j];
        xx = (xx > 0.0f) ? xx : (expf(xx) - 1.0f);
        r[j] = (xx - mu[c + j]) * rsqrtf(var[c + j] + EPS_BN) * g[c + j] + bt[c + j];
    }
    ((__nv_bfloat162*)out)[2 * i4]     = __floats2bfloat162_rn(r[0], r[1]);
    ((__nv_bfloat162*)out)[2 * i4 + 1] = __floats2bfloat162_rn(r[2], r[3]);
}

// ---------------- head mean + bias + BN2 + pooling --------------------------
__global__ void mean_bn2_pool(const float* __restrict__ out2,
                              const int* __restrict__ batch,
                              const float* __restrict__ b2,
                              const float* __restrict__ g2,
                              const float* __restrict__ bt2,
                              const float* __restrict__ mu2,
                              const float* __restrict__ var2) {
    int n = blockIdx.x * (blockDim.x / 32) + (threadIdx.x >> 5);
    int lane = threadIdx.x & 31;
    if (n >= N_NODES) return;
    const float* row = out2 + (size_t)n * D1;
    float s = 0.0f;
    #pragma unroll 8
    for (int hd = 0; hd < HEADS; hd++) s += row[hd * 32 + lane];
    s = s * (1.0f / HEADS) + b2[lane];
    s = (s - mu2[lane]) * rsqrtf(var2[lane] + EPS_BN) * g2[lane] + bt2[lane];
    int gi = batch[n];
    atomicAdd(&g_pool[gi * OUTD + lane], s);
    if (lane == 0) atomicAdd(&g_cnt[gi], 1.0f);
}

// ---------------- final linear ----------------------------------------------
__global__ void final_lin(const float* __restrict__ lin_w,
                          const float* __restrict__ lin_b,
                          float* __restrict__ out) {
    int i = blockIdx.x * blockDim.x + threadIdx.x;
    if (i >= N_GRAPHS * N_CLASS) return;
    int g = i / N_CLASS, c = i - g * N_CLASS;
    float cnt = fmaxf(g_cnt[g], 1.0f);
    float acc = lin_b[c];
    #pragma unroll
    for (int k = 0; k < OUTD; k++)
        acc += (g_pool[g * OUTD + k] / cnt) * lin_w[k * N_CLASS + c];
    out[i] = acc;
}

// ---------------- host orchestration ----------------------------------------
extern "C" void kernel_launch(void* const* d_in, const int* in_sizes, int n_in,
                              void* d_out, int out_size) {
    const float* x        = (const float*)d_in[0];
    const int*   ei       = (const int*)  d_in[1];
    const int*   batch    = (const int*)  d_in[2];
    const float* W1       = (const float*)d_in[3];
    const float* att_src1 = (const float*)d_in[4];
    const float* att_dst1 = (const float*)d_in[5];
    const float* b1       = (const float*)d_in[6];
    const float* bn1_g    = (const float*)d_in[7];
    const float* bn1_b    = (const float*)d_in[8];
    const float* bn1_m    = (const float*)d_in[9];
    const float* bn1_v    = (const float*)d_in[10];
    const float* W2       = (const float*)d_in[11];
    const float* att_src2 = (const float*)d_in[12];
    const float* att_dst2 = (const float*)d_in[13];
    const float* b2       = (const float*)d_in[14];
    const float* bn2_g    = (const float*)d_in[15];
    const float* bn2_b    = (const float*)d_in[16];
    const float* bn2_m    = (const float*)d_in[17];
    const float* bn2_v    = (const float*)d_in[18];
    const float* lin_w    = (const float*)d_in[19];
    const float* lin_b    = (const float*)d_in[20];
    float* out = (float*)d_out;

    float *bufA, *bufB, *m_ptr, *den_ptr, *pool_ptr, *cnt_ptr;
    __nv_bfloat16 *xbf, *w1t, *w2t, *actbf;
    cudaGetSymbolAddress((void**)&bufA,    g_bufA);
    cudaGetSymbolAddress((void**)&bufB,    g_bufB);
    cudaGetSymbolAddress((void**)&m_ptr,   g_m);
    cudaGetSymbolAddress((void**)&den_ptr, g_den);
    cudaGetSymbolAddress((void**)&pool_ptr,g_pool);
    cudaGetSymbolAddress((void**)&cnt_ptr, g_cnt);
    cudaGetSymbolAddress((void**)&xbf,     g_xbf);
    cudaGetSymbolAddress((void**)&w1t,     g_w1t);
    cudaGetSymbolAddress((void**)&w2t,     g_w2t);
    cudaGetSymbolAddress((void**)&actbf,   g_actbf);

    const int NH  = N_NODES * HEADS;
    const int EH  = E_TOT * HEADS;
    const int ND1 = N_NODES * D1;
    const int NPOOL = N_GRAPHS * OUTD;
    const float NEG_INF = -__builtin_huge_valf();

    const int SMEM_BYTES = NSTAGE * STAGE_BYTES;   // 61440 B
    cudaFuncSetAttribute(bf16_gemm, cudaFuncAttributeMaxDynamicSharedMemorySize, SMEM_BYTES);

    dim3 gemmGrid(D1 / BN, (N_NODES + BM - 1) / BM);

    // ===== conversions + init fills =====
    cvt_bf16<<<(N_NODES * N_FEAT / 4 + 255) / 256, 256>>>(x, xbf, N_NODES * N_FEAT / 4);
    transpose_cvt<<<dim3(D1 / 32, N_FEAT / 32), dim3(32, 8)>>>(W1, w1t, N_FEAT, D1);
    transpose_cvt<<<dim3(D1 / 32, D1 / 32), dim3(32, 8)>>>(W2, w2t, D1, D1);
    fill_kernel<<<(NH + 255) / 256, 256>>>(m_ptr, NEG_INF, NH);
    fill_kernel<<<(NH + 255) / 256, 256>>>(den_ptr, 0.0f, NH);
    fill_kernel<<<(ND1 + 255) / 256, 256>>>(bufB, 0.0f, ND1);
    fill_kernel<<<(NPOOL + 255) / 256, 256>>>(pool_ptr, 0.0f, NPOOL);
    fill_kernel<<<1, 64>>>(cnt_ptr, 0.0f, N_GRAPHS);

    // ===== layer 1 =====
    bf16_gemm<<<gemmGrid, 256, SMEM_BYTES>>>(xbf, w1t, bufA, N_NODES, D1, N_FEAT);  // h1
    attn_scores<<<(N_NODES + 7) / 8, 256>>>(bufA, att_src1, att_dst1);
    edge_max<<<(EH + 255) / 256, 256>>>(ei);
    edge_exp<<<(EH + 255) / 256, 256>>>(ei);
    aggregate<<<E_TOT, 128>>>(ei, bufA, bufB);                                      // out1 in bufB
    elu_bn1<<<(ND1 / 4 + 255) / 256, 256>>>(bufB, actbf, b1, bn1_g, bn1_b, bn1_m, bn1_v);

    // ===== layer 2 =====
    bf16_gemm<<<gemmGrid, 256, SMEM_BYTES>>>(actbf, w2t, bufB, N_NODES, D1, D1);    // h2 in bufB
    attn_scores<<<(N_NODES + 7) / 8, 256>>>(bufB, att_src2, att_dst2);
    fill_kernel<<<(NH + 255) / 256, 256>>>(m_ptr, NEG_INF, NH);
    fill_kernel<<<(NH + 255) / 256, 256>>>(den_ptr, 0.0f, NH);
    fill_kernel<<<(ND1 + 255) / 256, 256>>>(bufA, 0.0f, ND1);
    edge_max<<<(EH + 255) / 256, 256>>>(ei);
    edge_exp<<<(EH + 255) / 256, 256>>>(ei);
    aggregate<<<E_TOT, 128>>>(ei, bufB, bufA);                                      // out2 in bufA

    // ===== head-mean + BN2 + pool + linear =====
    mean_bn2_pool<<<(N_NODES + 7) / 8, 256>>>(bufA, batch, b2, bn2_g, bn2_b, bn2_m, bn2_v);
    final_lin<<<1, 128>>>(lin_w, lin_b, out);
}

// round 5
// speedup vs baseline: 2.9753x; 1.1200x over previous
#include <cuda_runtime.h>
#include <cuda_bf16.h>
#include <math.h>
#include <stdint.h>

#define N_NODES  20000
#define N_FEAT   128
#define HEADS    56
#define OUTD     32
#define D1       1792      // HEADS*OUTD
#define N_EDGES  100000
#define E_TOT    120000    // + self loops
#define N_GRAPHS 50
#define N_CLASS  2
#define EPS_BN   1e-5f

// ---------------- scratch (static device memory; no allocations) ------------
__device__ float g_agg[(size_t)N_NODES * D1];            // 143 MB f32 aggregate out
__device__ __nv_bfloat16 g_hbf [(size_t)N_NODES * D1];   // 71.7 MB bf16 h (per layer)
__device__ __nv_bfloat16 g_actbf[(size_t)N_NODES * D1];  // 71.7 MB bf16 activations
__device__ __nv_bfloat16 g_xbf [(size_t)N_NODES * N_FEAT];
__device__ __nv_bfloat16 g_w1t [(size_t)D1 * N_FEAT];    // W1^T [N][K]
__device__ __nv_bfloat16 g_w2t [(size_t)D1 * D1];        // W2^T [N][K]
__device__ float g_as[N_NODES * HEADS];
__device__ float g_ad[N_NODES * HEADS];
__device__ float g_m [N_NODES * HEADS];
__device__ float g_den[N_NODES * HEADS];
__device__ float g_ex[(size_t)E_TOT * HEADS];
__device__ float g_pool[N_GRAPHS * OUTD];
__device__ float g_cnt[N_GRAPHS];

// ---------------- helpers ---------------------------------------------------
// sign-split float atomic max; init pattern 0xFFFFFFFF acts as -inf:
//   int path (val>=0): stored -1 (int) < any positive float repr -> replaced
//   uint path (val<0): stored 0xFFFFFFFF is max unsigned -> any val replaces
__device__ __forceinline__ void atomicMaxF(float* addr, float val) {
    if (val >= 0.0f) atomicMax((int*)addr, __float_as_int(val));
    else             atomicMin((unsigned int*)addr, __float_as_uint(val));
}

__device__ __forceinline__ void redAddV4(float* addr, float a, float b, float c, float d) {
    asm volatile("red.global.add.v4.f32 [%0], {%1, %2, %3, %4};"
                 :: "l"(addr), "f"(a), "f"(b), "f"(c), "f"(d) : "memory");
}

__device__ __forceinline__ void cpAsync16(uint32_t smem_addr, const void* gptr, int src_bytes) {
    asm volatile("cp.async.ca.shared.global [%0], [%1], 16, %2;"
                 :: "r"(smem_addr), "l"(gptr), "r"(src_bytes));
}
__device__ __forceinline__ void cpCommit() { asm volatile("cp.async.commit_group;"); }
template <int N>
__device__ __forceinline__ void cpWait() { asm volatile("cp.async.wait_group %0;" :: "n"(N)); }

// ---------------- f32 -> bf16 elementwise (vector of 4) ---------------------
__global__ void cvt_bf16(const float* __restrict__ in, __nv_bfloat16* __restrict__ out, int n4) {
    int i = blockIdx.x * blockDim.x + threadIdx.x;
    if (i >= n4) return;
    float4 v = ((const float4*)in)[i];
    ((__nv_bfloat162*)out)[2 * i]     = __floats2bfloat162_rn(v.x, v.y);
    ((__nv_bfloat162*)out)[2 * i + 1] = __floats2bfloat162_rn(v.z, v.w);
}

// ---------------- f32 [K][N] -> bf16 [N][K] tiled transpose -----------------
__global__ void transpose_cvt(const float* __restrict__ in, __nv_bfloat16* __restrict__ out,
                              int K, int N) {
    __shared__ float tile[32][33];
    int k0 = blockIdx.y * 32, n0 = blockIdx.x * 32;
    #pragma unroll
    for (int j = 0; j < 4; j++) {
        int kk = threadIdx.y + j * 8;
        tile[kk][threadIdx.x] = in[(size_t)(k0 + kk) * N + n0 + threadIdx.x];
    }
    __syncthreads();
    #pragma unroll
    for (int j = 0; j < 4; j++) {
        int nn = threadIdx.y + j * 8;
        out[(size_t)(n0 + nn) * K + k0 + threadIdx.x] = __float2bfloat16(tile[threadIdx.x][nn]);
    }
}

// ---------------- BF16 tensor-core GEMM: C[M,N] = A[M,K] @ BT[N,K]^T --------
// A: bf16 [M][K]. BT: bf16 [N][K]. C: bf16 [M][N].
// 128x128x32 tiles, 8 warps (2x4), 64x32 warp tiles, mma.m16n8k16, 3 stages.
#define BM 128
#define BN 128
#define BK 32
#define TS 40                       // smem row stride in bf16 (pad 8)
#define A_ELE (BM * TS)             // 5120 bf16
#define STAGE_BYTES (2 * A_ELE * 2) // A + B tiles = 20480 B
#define NSTAGE 3

__global__ __launch_bounds__(256, 2) void bf16_gemm(const __nv_bfloat16* __restrict__ A,
                                                    const __nv_bfloat16* __restrict__ BT,
                                                    __nv_bfloat16* __restrict__ C,
                                                    int M, int N, int K) {
    extern __shared__ __nv_bfloat16 smem[];
    const int tid   = threadIdx.x;
    const int wid   = tid >> 5;
    const int lane  = tid & 31;
    const int g     = lane >> 2;
    const int t     = lane & 3;
    const int warpM = wid & 1;
    const int warpN = wid >> 1;
    const int rowBase = blockIdx.y * BM;
    const int colBase = blockIdx.x * BN;

    float acc[4][4][4];
    #pragma unroll
    for (int i = 0; i < 4; i++)
        #pragma unroll
        for (int j = 0; j < 4; j++)
            #pragma unroll
            for (int k = 0; k < 4; k++) acc[i][j][k] = 0.0f;

    uint32_t smemBase = (uint32_t)__cvta_generic_to_shared(smem);
    const int T = K / BK;

    auto load_tiles = [&](int it, int stage) {
        int k0 = it * BK;
        uint32_t sA = smemBase + stage * STAGE_BYTES;
        uint32_t sB = sA + A_ELE * 2;
        #pragma unroll
        for (int j = 0; j < 2; j++) {
            int idx = tid + j * 256;          // 0..511
            int m   = idx >> 2;               // 0..127
            int c8  = (idx & 3) * 8;          // 0,8,16,24
            int gr  = rowBase + m;
            const __nv_bfloat16* src = A + (size_t)(gr < M ? gr : 0) * K + k0 + c8;
            cpAsync16(sA + (m * TS + c8) * 2, src, (gr < M) ? 16 : 0);
        }
        #pragma unroll
        for (int j = 0; j < 2; j++) {
            int idx = tid + j * 256;
            int n   = idx >> 2;
            int c8  = (idx & 3) * 8;
            const __nv_bfloat16* src = BT + (size_t)(colBase + n) * K + k0 + c8;
            cpAsync16(sB + (n * TS + c8) * 2, src, 16);
        }
    };

    load_tiles(0, 0);
    cpCommit();
    if (T > 1) load_tiles(1, 1);
    cpCommit();

    for (int it = 0; it < T; ++it) {
        cpWait<1>();
        __syncthreads();
        if (it + 2 < T) load_tiles(it + 2, (it + 2) % NSTAGE);
        cpCommit();

        const __nv_bfloat16* As_s = smem + (it % NSTAGE) * (STAGE_BYTES / 2);
        const __nv_bfloat16* Bs_s = As_s + A_ELE;

        #pragma unroll
        for (int ks = 0; ks < 2; ks++) {
            uint32_t af[4][4], bf[4][2];
            #pragma unroll
            for (int mt = 0; mt < 4; mt++) {
                int r = warpM * 64 + mt * 16 + g;
                const __nv_bfloat16* p = &As_s[r * TS + ks * 16 + 2 * t];
                af[mt][0] = *(const uint32_t*)&p[0];
                af[mt][1] = *(const uint32_t*)&p[8 * TS];
                af[mt][2] = *(const uint32_t*)&p[8];
                af[mt][3] = *(const uint32_t*)&p[8 * TS + 8];
            }
            #pragma unroll
            for (int nt = 0; nt < 4; nt++) {
                int c = warpN * 32 + nt * 8 + g;
                const __nv_bfloat16* p = &Bs_s[c * TS + ks * 16 + 2 * t];
                bf[nt][0] = *(const uint32_t*)&p[0];
                bf[nt][1] = *(const uint32_t*)&p[8];
            }
            #pragma unroll
            for (int mt = 0; mt < 4; mt++)
                #pragma unroll
                for (int nt = 0; nt < 4; nt++) {
                    float* d = acc[mt][nt];
                    asm volatile(
                        "mma.sync.aligned.m16n8k16.row.col.f32.bf16.bf16.f32 "
                        "{%0,%1,%2,%3}, {%4,%5,%6,%7}, {%8,%9}, {%0,%1,%2,%3};"
                        : "+f"(d[0]), "+f"(d[1]), "+f"(d[2]), "+f"(d[3])
                        : "r"(af[mt][0]), "r"(af[mt][1]), "r"(af[mt][2]), "r"(af[mt][3]),
                          "r"(bf[nt][0]), "r"(bf[nt][1]));
                }
        }
        __syncthreads();
    }

    #pragma unroll
    for (int mt = 0; mt < 4; mt++) {
        int r0 = rowBase + warpM * 64 + mt * 16 + g;
        #pragma unroll
        for (int nt = 0; nt < 4; nt++) {
            int c = colBase + warpN * 32 + nt * 8 + 2 * t;
            if (r0 < M)
                *(__nv_bfloat162*)&C[(size_t)r0 * N + c] =
                    __floats2bfloat162_rn(acc[mt][nt][0], acc[mt][nt][1]);
            if (r0 + 8 < M)
                *(__nv_bfloat162*)&C[(size_t)(r0 + 8) * N + c] =
                    __floats2bfloat162_rn(acc[mt][nt][2], acc[mt][nt][3]);
        }
    }
}

// ---------------- attention scores a_s/a_d (bf16 h) --------------------------
__global__ void attn_scores(const __nv_bfloat16* __restrict__ h,
                            const float* __restrict__ att_s,
                            const float* __restrict__ att_d) {
    int n = blockIdx.x * (blockDim.x / 32) + (threadIdx.x >> 5);
    int lane = threadIdx.x & 31;
    if (n >= N_NODES) return;
    const __nv_bfloat16* hrow = h + (size_t)n * D1;
    for (int hd = 0; hd < HEADS; hd++) {
        float v = __bfloat162float(hrow[hd * 32 + lane]);
        float s = v * att_s[hd * 32 + lane];
        float d = v * att_d[hd * 32 + lane];
        #pragma unroll
        for (int o = 16; o; o >>= 1) {
            s += __shfl_down_sync(0xffffffffu, s, o);
            d += __shfl_down_sync(0xffffffffu, d, o);
        }
        if (lane == 0) {
            g_as[n * HEADS + hd] = s;
            g_ad[n * HEADS + hd] = d;
        }
    }
}

// ---------------- edge softmax: pass 1 (segment max) ------------------------
__global__ void edge_max(const int* __restrict__ ei) {
    int i = blockIdx.x * blockDim.x + threadIdx.x;
    if (i >= E_TOT * HEADS) return;
    int e = i / HEADS, hd = i - e * HEADS;
    int s, d;
    if (e < N_EDGES) { s = ei[e]; d = ei[N_EDGES + e]; }
    else             { s = d = e - N_EDGES; }
    float x = g_as[s * HEADS + hd] + g_ad[d * HEADS + hd];
    x = (x > 0.0f) ? x : 0.2f * x;
    atomicMaxF(&g_m[d * HEADS + hd], x);
}

// ---------------- edge softmax: pass 2 (exp + segment sum) ------------------
__global__ void edge_exp(const int* __restrict__ ei) {
    int i = blockIdx.x * blockDim.x + threadIdx.x;
    if (i >= E_TOT * HEADS) return;
    int e = i / HEADS, hd = i - e * HEADS;
    int s, d;
    if (e < N_EDGES) { s = ei[e]; d = ei[N_EDGES + e]; }
    else             { s = d = e - N_EDGES; }
    float x = g_as[s * HEADS + hd] + g_ad[d * HEADS + hd];
    x = (x > 0.0f) ? x : 0.2f * x;
    float ex = expf(x - g_m[d * HEADS + hd]);
    g_ex[(size_t)e * HEADS + hd] = ex;
    atomicAdd(&g_den[d * HEADS + hd], ex);
}

// ---------------- message aggregation: out[dst] += alpha * h[src] -----------
__global__ __launch_bounds__(128) void aggregate(const int* __restrict__ ei,
                                                 const __nv_bfloat16* __restrict__ h,
                                                 float* __restrict__ out) {
    int e = blockIdx.x;
    __shared__ float alpha[HEADS];
    int s, d;
    if (e < N_EDGES) { s = ei[e]; d = ei[N_EDGES + e]; }
    else             { s = d = e - N_EDGES; }
    int t = threadIdx.x;
    if (t < HEADS) alpha[t] = g_ex[(size_t)e * HEADS + t] / g_den[d * HEADS + t];
    __syncthreads();
    const __nv_bfloat16* hs = h + (size_t)s * D1;
    float* od = out + (size_t)d * D1;
    #pragma unroll
    for (int idx = t * 4; idx < D1; idx += 128 * 4) {
        float a = alpha[idx >> 5];
        __nv_bfloat162 p0 = *(const __nv_bfloat162*)&hs[idx];
        __nv_bfloat162 p1 = *(const __nv_bfloat162*)&hs[idx + 2];
        float2 f0 = __bfloat1622float2(p0);
        float2 f1 = __bfloat1622float2(p1);
        redAddV4(&od[idx], a * f0.x, a * f0.y, a * f1.x, a * f1.y);
    }
}

// ---------------- bias + ELU + BN1 -> bf16 output ---------------------------
__global__ void elu_bn1(const float* __restrict__ in, __nv_bfloat16* __restrict__ out,
                        const float* __restrict__ b,  const float* __restrict__ g,
                        const float* __restrict__ bt, const float* __restrict__ mu,
                        const float* __restrict__ var) {
    int i4 = blockIdx.x * blockDim.x + threadIdx.x;
    if (i4 >= N_NODES * D1 / 4) return;
    int i = i4 * 4;
    int c = i % D1;
    float4 v = *(const float4*)&in[i];
    float r[4] = {v.x, v.y, v.z, v.w};
    #pragma unroll
    for (int j = 0; j < 4; j++) {
        float xx = r[j] + b[c + j];
        xx = (xx > 0.0f) ? xx : (expf(xx) - 1.0f);
        r[j] = (xx - mu[c + j]) * rsqrtf(var[c + j] + EPS_BN) * g[c + j] + bt[c + j];
    }
    ((__nv_bfloat162*)out)[2 * i4]     = __floats2bfloat162_rn(r[0], r[1]);
    ((__nv_bfloat162*)out)[2 * i4 + 1] = __floats2bfloat162_rn(r[2], r[3]);
}

// ---------------- head mean + bias + BN2 + pooling --------------------------
__global__ void mean_bn2_pool(const float* __restrict__ out2,
                              const int* __restrict__ batch,
                              const float* __restrict__ b2,
                              const float* __restrict__ g2,
                              const float* __restrict__ bt2,
                              const float* __restrict__ mu2,
                              const float* __restrict__ var2) {
    int n = blockIdx.x * (blockDim.x / 32) + (threadIdx.x >> 5);
    int lane = threadIdx.x & 31;
    if (n >= N_NODES) return;
    const float* row = out2 + (size_t)n * D1;
    float s = 0.0f;
    #pragma unroll 8
    for (int hd = 0; hd < HEADS; hd++) s += row[hd * 32 + lane];
    s = s * (1.0f / HEADS) + b2[lane];
    s = (s - mu2[lane]) * rsqrtf(var2[lane] + EPS_BN) * g2[lane] + bt2[lane];
    int gi = batch[n];
    atomicAdd(&g_pool[gi * OUTD + lane], s);
    if (lane == 0) atomicAdd(&g_cnt[gi], 1.0f);
}

// ---------------- final linear ----------------------------------------------
__global__ void final_lin(const float* __restrict__ lin_w,
                          const float* __restrict__ lin_b,
                          float* __restrict__ out) {
    int i = blockIdx.x * blockDim.x + threadIdx.x;
    if (i >= N_GRAPHS * N_CLASS) return;
    int g = i / N_CLASS, c = i - g * N_CLASS;
    float cnt = fmaxf(g_cnt[g], 1.0f);
    float acc = lin_b[c];
    #pragma unroll
    for (int k = 0; k < OUTD; k++)
        acc += (g_pool[g * OUTD + k] / cnt) * lin_w[k * N_CLASS + c];
    out[i] = acc;
}

// ---------------- host orchestration ----------------------------------------
extern "C" void kernel_launch(void* const* d_in, const int* in_sizes, int n_in,
                              void* d_out, int out_size) {
    const float* x        = (const float*)d_in[0];
    const int*   ei       = (const int*)  d_in[1];
    const int*   batch    = (const int*)  d_in[2];
    const float* W1       = (const float*)d_in[3];
    const float* att_src1 = (const float*)d_in[4];
    const float* att_dst1 = (const float*)d_in[5];
    const float* b1       = (const float*)d_in[6];
    const float* bn1_g    = (const float*)d_in[7];
    const float* bn1_b    = (const float*)d_in[8];
    const float* bn1_m    = (const float*)d_in[9];
    const float* bn1_v    = (const float*)d_in[10];
    const float* W2       = (const float*)d_in[11];
    const float* att_src2 = (const float*)d_in[12];
    const float* att_dst2 = (const float*)d_in[13];
    const float* b2       = (const float*)d_in[14];
    const float* bn2_g    = (const float*)d_in[15];
    const float* bn2_b    = (const float*)d_in[16];
    const float* bn2_m    = (const float*)d_in[17];
    const float* bn2_v    = (const float*)d_in[18];
    const float* lin_w    = (const float*)d_in[19];
    const float* lin_b    = (const float*)d_in[20];
    float* out = (float*)d_out;

    float *agg, *m_ptr, *den_ptr, *pool_ptr, *cnt_ptr;
    __nv_bfloat16 *xbf, *w1t, *w2t, *actbf, *hbf;
    cudaGetSymbolAddress((void**)&agg,     g_agg);
    cudaGetSymbolAddress((void**)&m_ptr,   g_m);
    cudaGetSymbolAddress((void**)&den_ptr, g_den);
    cudaGetSymbolAddress((void**)&pool_ptr,g_pool);
    cudaGetSymbolAddress((void**)&cnt_ptr, g_cnt);
    cudaGetSymbolAddress((void**)&xbf,     g_xbf);
    cudaGetSymbolAddress((void**)&w1t,     g_w1t);
    cudaGetSymbolAddress((void**)&w2t,     g_w2t);
    cudaGetSymbolAddress((void**)&actbf,   g_actbf);
    cudaGetSymbolAddress((void**)&hbf,     g_hbf);

    const int NH  = N_NODES * HEADS;
    const int EH  = E_TOT * HEADS;
    const int ND1 = N_NODES * D1;

    const int SMEM_BYTES = NSTAGE * STAGE_BYTES;   // 61440 B
    cudaFuncSetAttribute(bf16_gemm, cudaFuncAttributeMaxDynamicSharedMemorySize, SMEM_BYTES);

    dim3 gemmGrid(D1 / BN, (N_NODES + BM - 1) / BM);

    // ===== conversions + init memsets (HW memset path) =====
    cvt_bf16<<<(N_NODES * N_FEAT / 4 + 255) / 256, 256>>>(x, xbf, N_NODES * N_FEAT / 4);
    transpose_cvt<<<dim3(D1 / 32, N_FEAT / 32), dim3(32, 8)>>>(W1, w1t, N_FEAT, D1);
    transpose_cvt<<<dim3(D1 / 32, D1 / 32), dim3(32, 8)>>>(W2, w2t, D1, D1);
    cudaMemsetAsync(m_ptr,   0xFF, (size_t)NH * 4);      // acts as -inf (see atomicMaxF)
    cudaMemsetAsync(den_ptr, 0,    (size_t)NH * 4);
    cudaMemsetAsync(agg,     0,    (size_t)ND1 * 4);
    cudaMemsetAsync(pool_ptr,0,    (size_t)N_GRAPHS * OUTD * 4);
    cudaMemsetAsync(cnt_ptr, 0,    (size_t)N_GRAPHS * 4);

    // ===== layer 1 =====
    bf16_gemm<<<gemmGrid, 256, SMEM_BYTES>>>(xbf, w1t, hbf, N_NODES, D1, N_FEAT);   // h1 (bf16)
    attn_scores<<<(N_NODES + 7) / 8, 256>>>(hbf, att_src1, att_dst1);
    edge_max<<<(EH + 255) / 256, 256>>>(ei);
    edge_exp<<<(EH + 255) / 256, 256>>>(ei);
    aggregate<<<E_TOT, 128>>>(ei, hbf, agg);                                        // out1 f32
    elu_bn1<<<(ND1 / 4 + 255) / 256, 256>>>(agg, actbf, b1, bn1_g, bn1_b, bn1_m, bn1_v);

    // ===== layer 2 =====
    bf16_gemm<<<gemmGrid, 256, SMEM_BYTES>>>(actbf, w2t, hbf, N_NODES, D1, D1);     // h2 (bf16)
    attn_scores<<<(N_NODES + 7) / 8, 256>>>(hbf, att_src2, att_dst2);
    cudaMemsetAsync(m_ptr,   0xFF, (size_t)NH * 4);
    cudaMemsetAsync(den_ptr, 0,    (size_t)NH * 4);
    cudaMemsetAsync(agg,     0,    (size_t)ND1 * 4);
    edge_max<<<(EH + 255) / 256, 256>>>(ei);
    edge_exp<<<(EH + 255) / 256, 256>>>(ei);
    aggregate<<<E_TOT, 128>>>(ei, hbf, agg);                                        // out2 f32

    // ===== head-mean + BN2 + pool + linear =====
    mean_bn2_pool<<<(N_NODES + 7) / 8, 256>>>(agg, batch, b2, bn2_g, bn2_b, bn2_m, bn2_v);
    final_lin<<<1, 128>>>(lin_w, lin_b, out);
}

// round 6
// speedup vs baseline: 3.1006x; 1.0421x over previous
#include <cuda_runtime.h>
#include <cuda_bf16.h>
#include <math.h>
#include <stdint.h>

#define N_NODES  20000
#define N_FEAT   128
#define HEADS    56
#define OUTD     32
#define D1       1792      // HEADS*OUTD
#define N_EDGES  100000
#define E_TOT    120000    // + self loops
#define N_GRAPHS 50
#define N_CLASS  2
#define EPS_BN   1e-5f

// ---------------- scratch (static device memory; no allocations) ------------
__device__ float g_agg[(size_t)N_NODES * D1];            // 143 MB f32 aggregate out
__device__ __nv_bfloat16 g_hbf [(size_t)N_NODES * D1];   // 71.7 MB bf16 h (per layer)
__device__ __nv_bfloat16 g_actbf[(size_t)N_NODES * D1];  // 71.7 MB bf16 activations
__device__ __nv_bfloat16 g_xbf [(size_t)N_NODES * N_FEAT];
__device__ __nv_bfloat16 g_w1t [(size_t)D1 * N_FEAT];    // W1^T [N][K]
__device__ __nv_bfloat16 g_w2t [(size_t)D1 * D1];        // W2^T [N][K]
__device__ float g_as[N_NODES * HEADS];
__device__ float g_ad[N_NODES * HEADS];
__device__ float g_m [N_NODES * HEADS];
__device__ float g_den[N_NODES * HEADS];
__device__ float g_ex[(size_t)E_TOT * HEADS];
__device__ float g_pool[N_GRAPHS * OUTD];
__device__ float g_cnt[N_GRAPHS];

// ---------------- helpers ---------------------------------------------------
// sign-split float atomic max; init pattern 0xFFFFFFFF acts as -inf.
__device__ __forceinline__ void atomicMaxF(float* addr, float val) {
    if (val >= 0.0f) atomicMax((int*)addr, __float_as_int(val));
    else             atomicMin((unsigned int*)addr, __float_as_uint(val));
}

__device__ __forceinline__ void redAddV4(float* addr, float a, float b, float c, float d) {
    asm volatile("red.global.add.v4.f32 [%0], {%1, %2, %3, %4};"
                 :: "l"(addr), "f"(a), "f"(b), "f"(c), "f"(d) : "memory");
}

__device__ __forceinline__ void cpAsync16(uint32_t smem_addr, const void* gptr, int src_bytes) {
    asm volatile("cp.async.ca.shared.global [%0], [%1], 16, %2;"
                 :: "r"(smem_addr), "l"(gptr), "r"(src_bytes));
}
__device__ __forceinline__ void cpCommit() { asm volatile("cp.async.commit_group;"); }
template <int N>
__device__ __forceinline__ void cpWait() { asm volatile("cp.async.wait_group %0;" :: "n"(N)); }

__device__ __forceinline__ void ldsmX4(uint32_t& r0, uint32_t& r1, uint32_t& r2, uint32_t& r3,
                                       uint32_t addr) {
    asm volatile("ldmatrix.sync.aligned.m8n8.x4.shared.b16 {%0,%1,%2,%3}, [%4];"
                 : "=r"(r0), "=r"(r1), "=r"(r2), "=r"(r3) : "r"(addr));
}

// ---------------- f32 -> bf16 elementwise (vector of 4) ---------------------
__global__ void cvt_bf16(const float* __restrict__ in, __nv_bfloat16* __restrict__ out, int n4) {
    int i = blockIdx.x * blockDim.x + threadIdx.x;
    if (i >= n4) return;
    float4 v = ((const float4*)in)[i];
    ((__nv_bfloat162*)out)[2 * i]     = __floats2bfloat162_rn(v.x, v.y);
    ((__nv_bfloat162*)out)[2 * i + 1] = __floats2bfloat162_rn(v.z, v.w);
}

// ---------------- f32 [K][N] -> bf16 [N][K] tiled transpose -----------------
__global__ void transpose_cvt(const float* __restrict__ in, __nv_bfloat16* __restrict__ out,
                              int K, int N) {
    __shared__ float tile[32][33];
    int k0 = blockIdx.y * 32, n0 = blockIdx.x * 32;
    #pragma unroll
    for (int j = 0; j < 4; j++) {
        int kk = threadIdx.y + j * 8;
        tile[kk][threadIdx.x] = in[(size_t)(k0 + kk) * N + n0 + threadIdx.x];
    }
    __syncthreads();
    #pragma unroll
    for (int j = 0; j < 4; j++) {
        int nn = threadIdx.y + j * 8;
        out[(size_t)(n0 + nn) * K + k0 + threadIdx.x] = __float2bfloat16(tile[threadIdx.x][nn]);
    }
}

// ---------------- BF16 tensor-core GEMM: C[M,N] = A[M,K] @ BT[N,K]^T --------
// A: bf16 [M][K]. BT: bf16 [N][K]. C: bf16 [M][N].
// 128x128x32 tiles, 8 warps (2x4), 64x32 warp tiles, mma.m16n8k16,
// ldmatrix.x4 fragment loads, 4-stage cp.async pipeline, 1 sync per k-iter.
#define BM 128
#define BN 128
#define BK 32
#define TS 40                       // smem row stride in bf16 (pad 8)
#define A_ELE (BM * TS)             // 5120 bf16
#define STAGE_BYTES (2 * A_ELE * 2) // A + B tiles = 20480 B
#define NSTAGE 4

__global__ __launch_bounds__(256, 2) void bf16_gemm(const __nv_bfloat16* __restrict__ A,
                                                    const __nv_bfloat16* __restrict__ BT,
                                                    __nv_bfloat16* __restrict__ C,
                                                    int M, int N, int K) {
    extern __shared__ __nv_bfloat16 smem[];
    const int tid   = threadIdx.x;
    const int wid   = tid >> 5;
    const int lane  = tid & 31;
    const int g     = lane >> 2;
    const int t     = lane & 3;
    const int warpM = wid & 1;
    const int warpN = wid >> 1;
    const int rowBase = blockIdx.y * BM;
    const int colBase = blockIdx.x * BN;

    float acc[4][4][4];
    #pragma unroll
    for (int i = 0; i < 4; i++)
        #pragma unroll
        for (int j = 0; j < 4; j++)
            #pragma unroll
            for (int k = 0; k < 4; k++) acc[i][j][k] = 0.0f;

    uint32_t smemBase = (uint32_t)__cvta_generic_to_shared(smem);
    const int T = K / BK;

    // ldmatrix lane addressing
    const int laneRow  = lane & 15;
    const int laneHalf = lane >> 4;
    const uint32_t aOff = ((warpM * 64 + laneRow) * TS + laneHalf * 8) * 2;
    const uint32_t bOff = (uint32_t)A_ELE * 2 + ((warpN * 32 + laneRow) * TS + laneHalf * 8) * 2;

    auto load_tiles = [&](int it, int stage) {
        int k0 = it * BK;
        uint32_t sA = smemBase + stage * STAGE_BYTES;
        uint32_t sB = sA + A_ELE * 2;
        #pragma unroll
        for (int j = 0; j < 2; j++) {
            int idx = tid + j * 256;          // 0..511
            int m   = idx >> 2;               // 0..127
            int c8  = (idx & 3) * 8;          // 0,8,16,24
            int gr  = rowBase + m;
            const __nv_bfloat16* src = A + (size_t)(gr < M ? gr : 0) * K + k0 + c8;
            cpAsync16(sA + (m * TS + c8) * 2, src, (gr < M) ? 16 : 0);
        }
        #pragma unroll
        for (int j = 0; j < 2; j++) {
            int idx = tid + j * 256;
            int n   = idx >> 2;
            int c8  = (idx & 3) * 8;
            const __nv_bfloat16* src = BT + (size_t)(colBase + n) * K + k0 + c8;
            cpAsync16(sB + (n * TS + c8) * 2, src, 16);
        }
    };

    #pragma unroll
    for (int s = 0; s < 3; s++) {
        if (s < T) load_tiles(s, s);
        cpCommit();
    }

    for (int it = 0; it < T; ++it) {
        cpWait<2>();
        __syncthreads();
        if (it + 3 < T) load_tiles(it + 3, (it + 3) & (NSTAGE - 1));
        cpCommit();

        uint32_t sStage = smemBase + (it & (NSTAGE - 1)) * STAGE_BYTES;

        #pragma unroll
        for (int ks = 0; ks < 2; ks++) {
            uint32_t af[4][4], bf[4][2];
            #pragma unroll
            for (int mt = 0; mt < 4; mt++)
                ldsmX4(af[mt][0], af[mt][1], af[mt][2], af[mt][3],
                       sStage + aOff + (mt * 16 * TS + ks * 16) * 2);
            #pragma unroll
            for (int nt2 = 0; nt2 < 2; nt2++)
                ldsmX4(bf[2 * nt2][0], bf[2 * nt2 + 1][0], bf[2 * nt2][1], bf[2 * nt2 + 1][1],
                       sStage + bOff + (nt2 * 16 * TS + ks * 16) * 2);
            #pragma unroll
            for (int mt = 0; mt < 4; mt++)
                #pragma unroll
                for (int nt = 0; nt < 4; nt++) {
                    float* d = acc[mt][nt];
                    asm volatile(
                        "mma.sync.aligned.m16n8k16.row.col.f32.bf16.bf16.f32 "
                        "{%0,%1,%2,%3}, {%4,%5,%6,%7}, {%8,%9}, {%0,%1,%2,%3};"
                        : "+f"(d[0]), "+f"(d[1]), "+f"(d[2]), "+f"(d[3])
                        : "r"(af[mt][0]), "r"(af[mt][1]), "r"(af[mt][2]), "r"(af[mt][3]),
                          "r"(bf[nt][0]), "r"(bf[nt][1]));
                }
        }
    }

    #pragma unroll
    for (int mt = 0; mt < 4; mt++) {
        int r0 = rowBase + warpM * 64 + mt * 16 + g;
        #pragma unroll
        for (int nt = 0; nt < 4; nt++) {
            int c = colBase + warpN * 32 + nt * 8 + 2 * t;
            if (r0 < M)
                *(__nv_bfloat162*)&C[(size_t)r0 * N + c] =
                    __floats2bfloat162_rn(acc[mt][nt][0], acc[mt][nt][1]);
            if (r0 + 8 < M)
                *(__nv_bfloat162*)&C[(size_t)(r0 + 8) * N + c] =
                    __floats2bfloat162_rn(acc[mt][nt][2], acc[mt][nt][3]);
        }
    }
}

// ---------------- attention scores a_s/a_d (bf16 h) --------------------------
__global__ void attn_scores(const __nv_bfloat16* __restrict__ h,
                            const float* __restrict__ att_s,
                            const float* __restrict__ att_d) {
    int n = blockIdx.x * (blockDim.x / 32) + (threadIdx.x >> 5);
    int lane = threadIdx.x & 31;
    if (n >= N_NODES) return;
    const __nv_bfloat16* hrow = h + (size_t)n * D1;
    for (int hd = 0; hd < HEADS; hd++) {
        float v = __bfloat162float(hrow[hd * 32 + lane]);
        float s = v * att_s[hd * 32 + lane];
        float d = v * att_d[hd * 32 + lane];
        #pragma unroll
        for (int o = 16; o; o >>= 1) {
            s += __shfl_down_sync(0xffffffffu, s, o);
            d += __shfl_down_sync(0xffffffffu, d, o);
        }
        if (lane == 0) {
            g_as[n * HEADS + hd] = s;
            g_ad[n * HEADS + hd] = d;
        }
    }
}

// ---------------- edge softmax: pass 1 (segment max) ------------------------
__global__ void edge_max(const int* __restrict__ ei) {
    int i = blockIdx.x * blockDim.x + threadIdx.x;
    if (i >= E_TOT * HEADS) return;
    int e = i / HEADS, hd = i - e * HEADS;
    int s, d;
    if (e < N_EDGES) { s = ei[e]; d = ei[N_EDGES + e]; }
    else             { s = d = e - N_EDGES; }
    float x = g_as[s * HEADS + hd] + g_ad[d * HEADS + hd];
    x = (x > 0.0f) ? x : 0.2f * x;
    atomicMaxF(&g_m[d * HEADS + hd], x);
}

// ---------------- edge softmax: pass 2 (exp + segment sum) ------------------
__global__ void edge_exp(const int* __restrict__ ei) {
    int i = blockIdx.x * blockDim.x + threadIdx.x;
    if (i >= E_TOT * HEADS) return;
    int e = i / HEADS, hd = i - e * HEADS;
    int s, d;
    if (e < N_EDGES) { s = ei[e]; d = ei[N_EDGES + e]; }
    else             { s = d = e - N_EDGES; }
    float x = g_as[s * HEADS + hd] + g_ad[d * HEADS + hd];
    x = (x > 0.0f) ? x : 0.2f * x;
    float ex = expf(x - g_m[d * HEADS + hd]);
    g_ex[(size_t)e * HEADS + hd] = ex;
    atomicAdd(&g_den[d * HEADS + hd], ex);
}

// ---------------- message aggregation: out[dst] += alpha * h[src] -----------
__global__ __launch_bounds__(128) void aggregate(const int* __restrict__ ei,
                                                 const __nv_bfloat16* __restrict__ h,
                                                 float* __restrict__ out) {
    int e = blockIdx.x;
    __shared__ float alpha[HEADS];
    int s, d;
    if (e < N_EDGES) { s = ei[e]; d = ei[N_EDGES + e]; }
    else             { s = d = e - N_EDGES; }
    int t = threadIdx.x;
    if (t < HEADS) alpha[t] = g_ex[(size_t)e * HEADS + t] / g_den[d * HEADS + t];
    __syncthreads();
    const __nv_bfloat16* hs = h + (size_t)s * D1;
    float* od = out + (size_t)d * D1;
    #pragma unroll
    for (int idx = t * 4; idx < D1; idx += 128 * 4) {
        float a = alpha[idx >> 5];
        __nv_bfloat162 p0 = *(const __nv_bfloat162*)&hs[idx];
        __nv_bfloat162 p1 = *(const __nv_bfloat162*)&hs[idx + 2];
        float2 f0 = __bfloat1622float2(p0);
        float2 f1 = __bfloat1622float2(p1);
        redAddV4(&od[idx], a * f0.x, a * f0.y, a * f1.x, a * f1.y);
    }
}

// ---------------- bias + ELU + BN1 -> bf16 output ---------------------------
__global__ void elu_bn1(const float* __restrict__ in, __nv_bfloat16* __restrict__ out,
                        const float* __restrict__ b,  const float* __restrict__ g,
                        const float* __restrict__ bt, const float* __restrict__ mu,
                        const float* __restrict__ var) {
    int i4 = blockIdx.x * blockDim.x + threadIdx.x;
    if (i4 >= N_NODES * D1 / 4) return;
    int i = i4 * 4;
    int c = i % D1;
    float4 v = *(const float4*)&in[i];
    float r[4] = {v.x, v.y, v.z, v.w};
    #pragma unroll
    for (int j = 0; j < 4; j++) {
        float xx = r[j] + b[c + j];
        xx = (xx > 0.0f) ? xx : (expf(xx) - 1.0f);
        r[j] = (xx - mu[c + j]) * rsqrtf(var[c + j] + EPS_BN) * g[c + j] + bt[c + j];
    }
    ((__nv_bfloat162*)out)[2 * i4]     = __floats2bfloat162_rn(r[0], r[1]);
    ((__nv_bfloat162*)out)[2 * i4 + 1] = __floats2bfloat162_rn(r[2], r[3]);
}

// ---------------- head mean + bias + BN2 + pooling --------------------------
__global__ void mean_bn2_pool(const float* __restrict__ out2,
                              const int* __restrict__ batch,
                              const float* __restrict__ b2,
                              const float* __restrict__ g2,
                              const float* __restrict__ bt2,
                              const float* __restrict__ mu2,
                              const float* __restrict__ var2) {
    int n = blockIdx.x * (blockDim.x / 32) + (threadIdx.x >> 5);
    int lane = threadIdx.x & 31;
    if (n >= N_NODES) return;
    const float* row = out2 + (size_t)n * D1;
    float s = 0.0f;
    #pragma unroll 8
    for (int hd = 0; hd < HEADS; hd++) s += row[hd * 32 + lane];
    s = s * (1.0f / HEADS) + b2[lane];
    s = (s - mu2[lane]) * rsqrtf(var2[lane] + EPS_BN) * g2[lane] + bt2[lane];
    int gi = batch[n];
    atomicAdd(&g_pool[gi * OUTD + lane], s);
    if (lane == 0) atomicAdd(&g_cnt[gi], 1.0f);
}

// ---------------- final linear ----------------------------------------------
__global__ void final_lin(const float* __restrict__ lin_w,
                          const float* __restrict__ lin_b,
                          float* __restrict__ out) {
    int i = blockIdx.x * blockDim.x + threadIdx.x;
    if (i >= N_GRAPHS * N_CLASS) return;
    int g = i / N_CLASS, c = i - g * N_CLASS;
    float cnt = fmaxf(g_cnt[g], 1.0f);
    float acc = lin_b[c];
    #pragma unroll
    for (int k = 0; k < OUTD; k++)
        acc += (g_pool[g * OUTD + k] / cnt) * lin_w[k * N_CLASS + c];
    out[i] = acc;
}

// ---------------- host orchestration ----------------------------------------
extern "C" void kernel_launch(void* const* d_in, const int* in_sizes, int n_in,
                              void* d_out, int out_size) {
    const float* x        = (const float*)d_in[0];
    const int*   ei       = (const int*)  d_in[1];
    const int*   batch    = (const int*)  d_in[2];
    const float* W1       = (const float*)d_in[3];
    const float* att_src1 = (const float*)d_in[4];
    const float* att_dst1 = (const float*)d_in[5];
    const float* b1       = (const float*)d_in[6];
    const float* bn1_g    = (const float*)d_in[7];
    const float* bn1_b    = (const float*)d_in[8];
    const float* bn1_m    = (const float*)d_in[9];
    const float* bn1_v    = (const float*)d_in[10];
    const float* W2       = (const float*)d_in[11];
    const float* att_src2 = (const float*)d_in[12];
    const float* att_dst2 = (const float*)d_in[13];
    const float* b2       = (const float*)d_in[14];
    const float* bn2_g    = (const float*)d_in[15];
    const float* bn2_b    = (const float*)d_in[16];
    const float* bn2_m    = (const float*)d_in[17];
    const float* bn2_v    = (const float*)d_in[18];
    const float* lin_w    = (const float*)d_in[19];
    const float* lin_b    = (const float*)d_in[20];
    float* out = (float*)d_out;

    float *agg, *m_ptr, *den_ptr, *pool_ptr, *cnt_ptr;
    __nv_bfloat16 *xbf, *w1t, *w2t, *actbf, *hbf;
    cudaGetSymbolAddress((void**)&agg,     g_agg);
    cudaGetSymbolAddress((void**)&m_ptr,   g_m);
    cudaGetSymbolAddress((void**)&den_ptr, g_den);
    cudaGetSymbolAddress((void**)&pool_ptr,g_pool);
    cudaGetSymbolAddress((void**)&cnt_ptr, g_cnt);
    cudaGetSymbolAddress((void**)&xbf,     g_xbf);
    cudaGetSymbolAddress((void**)&w1t,     g_w1t);
    cudaGetSymbolAddress((void**)&w2t,     g_w2t);
    cudaGetSymbolAddress((void**)&actbf,   g_actbf);
    cudaGetSymbolAddress((void**)&hbf,     g_hbf);

    const int NH  = N_NODES * HEADS;
    const int EH  = E_TOT * HEADS;
    const int ND1 = N_NODES * D1;

    const int SMEM_BYTES = NSTAGE * STAGE_BYTES;   // 81920 B
    cudaFuncSetAttribute(bf16_gemm, cudaFuncAttributeMaxDynamicSharedMemorySize, SMEM_BYTES);

    dim3 gemmGrid(D1 / BN, (N_NODES + BM - 1) / BM);

    // ===== conversions + init memsets (HW memset path) =====
    cvt_bf16<<<(N_NODES * N_FEAT / 4 + 255) / 256, 256>>>(x, xbf, N_NODES * N_FEAT / 4);
    transpose_cvt<<<dim3(D1 / 32, N_FEAT / 32), dim3(32, 8)>>>(W1, w1t, N_FEAT, D1);
    transpose_cvt<<<dim3(D1 / 32, D1 / 32), dim3(32, 8)>>>(W2, w2t, D1, D1);
    cudaMemsetAsync(m_ptr,   0xFF, (size_t)NH * 4);      // acts as -inf (see atomicMaxF)
    cudaMemsetAsync(den_ptr, 0,    (size_t)NH * 4);
    cudaMemsetAsync(agg,     0,    (size_t)ND1 * 4);
    cudaMemsetAsync(pool_ptr,0,    (size_t)N_GRAPHS * OUTD * 4);
    cudaMemsetAsync(cnt_ptr, 0,    (size_t)N_GRAPHS * 4);

    // ===== layer 1 =====
    bf16_gemm<<<gemmGrid, 256, SMEM_BYTES>>>(xbf, w1t, hbf, N_NODES, D1, N_FEAT);   // h1 (bf16)
    attn_scores<<<(N_NODES + 7) / 8, 256>>>(hbf, att_src1, att_dst1);
    edge_max<<<(EH + 255) / 256, 256>>>(ei);
    edge_exp<<<(EH + 255) / 256, 256>>>(ei);
    aggregate<<<E_TOT, 128>>>(ei, hbf, agg);                                        // out1 f32
    elu_bn1<<<(ND1 / 4 + 255) / 256, 256>>>(agg, actbf, b1, bn1_g, bn1_b, bn1_m, bn1_v);

    // ===== layer 2 =====
    bf16_gemm<<<gemmGrid, 256, SMEM_BYTES>>>(actbf, w2t, hbf, N_NODES, D1, D1);     // h2 (bf16)
    attn_scores<<<(N_NODES + 7) / 8, 256>>>(hbf, att_src2, att_dst2);
    cudaMemsetAsync(m_ptr,   0xFF, (size_t)NH * 4);
    cudaMemsetAsync(den_ptr, 0,    (size_t)NH * 4);
    cudaMemsetAsync(agg,     0,    (size_t)ND1 * 4);
    edge_max<<<(EH + 255) / 256, 256>>>(ei);
    edge_exp<<<(EH + 255) / 256, 256>>>(ei);
    aggregate<<<E_TOT, 128>>>(ei, hbf, agg);                                        // out2 f32

    // ===== head-mean + BN2 + pool + linear =====
    mean_bn2_pool<<<(N_NODES + 7) / 8, 256>>>(agg, batch, b2, bn2_g, bn2_b, bn2_m, bn2_v);
    final_lin<<<1, 128>>>(lin_w, lin_b, out);
}

// round 8
// speedup vs baseline: 4.5442x; 1.4656x over previous
#include <cuda_runtime.h>
#include <cuda_bf16.h>
#include <math.h>
#include <stdint.h>

#define N_NODES  20000
#define N_FEAT   128
#define HEADS    56
#define OUTD     32
#define D1       1792      // HEADS*OUTD
#define N_EDGES  100000
#define E_TOT    120000    // + self loops
#define N_GRAPHS 50
#define N_CLASS  2
#define EPS_BN   1e-5f

// ---------------- scratch (static device memory; no allocations) ------------
__device__ __nv_bfloat16 g_hbf [(size_t)N_NODES * D1];   // bf16 h (per layer)
__device__ __nv_bfloat16 g_actbf[(size_t)N_NODES * D1];  // bf16 activations
__device__ __nv_bfloat16 g_xbf [(size_t)N_NODES * N_FEAT];
__device__ __nv_bfloat16 g_w1t [(size_t)D1 * N_FEAT];    // W1^T [N][K]
__device__ __nv_bfloat16 g_w2t [(size_t)D1 * D1];        // W2^T [N][K]
__device__ float g_as[N_NODES * HEADS];
__device__ float g_ad[N_NODES * HEADS];
__device__ int   g_deg[N_NODES];
__device__ int   g_rowptr[N_NODES + 1];
__device__ int   g_next[N_NODES];
__device__ int   g_csr[E_TOT];          // src per CSR slot (by dst)
__device__ float g_pool[N_GRAPHS * OUTD];
__device__ float g_cnt[N_GRAPHS];

// ---------------- helpers ---------------------------------------------------
// sign-split float atomic max (works on smem too); init bits 0xFFFFFFFF act as -inf
__device__ __forceinline__ void atomicMaxF(float* addr, float val) {
    if (val >= 0.0f) atomicMax((int*)addr, __float_as_int(val));
    else             atomicMin((unsigned int*)addr, __float_as_uint(val));
}

__device__ __forceinline__ void cpAsync16(uint32_t smem_addr, const void* gptr, int src_bytes) {
    asm volatile("cp.async.ca.shared.global [%0], [%1], 16, %2;"
                 :: "r"(smem_addr), "l"(gptr), "r"(src_bytes));
}
__device__ __forceinline__ void cpCommit() { asm volatile("cp.async.commit_group;"); }
template <int N>
__device__ __forceinline__ void cpWait() { asm volatile("cp.async.wait_group %0;" :: "n"(N)); }

__device__ __forceinline__ void ldsmX4(uint32_t& r0, uint32_t& r1, uint32_t& r2, uint32_t& r3,
                                       uint32_t addr) {
    asm volatile("ldmatrix.sync.aligned.m8n8.x4.shared.b16 {%0,%1,%2,%3}, [%4];"
                 : "=r"(r0), "=r"(r1), "=r"(r2), "=r"(r3) : "r"(addr));
}

__device__ __forceinline__ void edge_sd(const int* __restrict__ ei, int e, int& s, int& d) {
    if (e < N_EDGES) { s = ei[e]; d = ei[N_EDGES + e]; }
    else             { s = d = e - N_EDGES; }
}

// ---------------- f32 -> bf16 elementwise (vector of 4) ---------------------
__global__ void cvt_bf16(const float* __restrict__ in, __nv_bfloat16* __restrict__ out, int n4) {
    int i = blockIdx.x * blockDim.x + threadIdx.x;
    if (i >= n4) return;
    float4 v = ((const float4*)in)[i];
    ((__nv_bfloat162*)out)[2 * i]     = __floats2bfloat162_rn(v.x, v.y);
    ((__nv_bfloat162*)out)[2 * i + 1] = __floats2bfloat162_rn(v.z, v.w);
}

// ---------------- f32 [K][N] -> bf16 [N][K] tiled transpose -----------------
__global__ void transpose_cvt(const float* __restrict__ in, __nv_bfloat16* __restrict__ out,
                              int K, int N) {
    __shared__ float tile[32][33];
    int k0 = blockIdx.y * 32, n0 = blockIdx.x * 32;
    #pragma unroll
    for (int j = 0; j < 4; j++) {
        int kk = threadIdx.y + j * 8;
        tile[kk][threadIdx.x] = in[(size_t)(k0 + kk) * N + n0 + threadIdx.x];
    }
    __syncthreads();
    #pragma unroll
    for (int j = 0; j < 4; j++) {
        int nn = threadIdx.y + j * 8;
        out[(size_t)(n0 + nn) * K + k0 + threadIdx.x] = __float2bfloat16(tile[threadIdx.x][nn]);
    }
}

// ---------------- CSR build --------------------------------------------------
__global__ void count_deg(const int* __restrict__ ei) {
    int e = blockIdx.x * blockDim.x + threadIdx.x;
    if (e >= E_TOT) return;
    int s, d; edge_sd(ei, e, s, d);
    atomicAdd(&g_deg[d], 1);
}

__global__ void scan_rowptr() {
    __shared__ int sums[256];
    __shared__ int offs[257];
    const int CH = (N_NODES + 255) / 256;
    int t = threadIdx.x;
    int base = t * CH;
    int s = 0;
    for (int i = 0; i < CH; i++) {
        int idx = base + i;
        if (idx < N_NODES) s += g_deg[idx];
    }
    sums[t] = s;
    __syncthreads();
    if (t == 0) {
        int acc = 0;
        for (int i = 0; i < 256; i++) { offs[i] = acc; acc += sums[i]; }
        offs[256] = acc;
    }
    __syncthreads();
    int run = offs[t];
    for (int i = 0; i < CH; i++) {
        int idx = base + i;
        if (idx < N_NODES) { g_rowptr[idx] = run; run += g_deg[idx]; }
    }
    if (t == 255) g_rowptr[N_NODES] = offs[256];
}

__global__ void scatter_csr(const int* __restrict__ ei) {
    int e = blockIdx.x * blockDim.x + threadIdx.x;
    if (e >= E_TOT) return;
    int s, d; edge_sd(ei, e, s, d);
    int pos = atomicAdd(&g_next[d], 1);
    g_csr[pos] = s;
}

// ---------------- BF16 tensor-core GEMM (R6, known good) --------------------
#define BM 128
#define BN 128
#define BK 32
#define TS 40
#define A_ELE (BM * TS)
#define STAGE_BYTES (2 * A_ELE * 2)
#define NSTAGE 4

__global__ __launch_bounds__(256, 2) void bf16_gemm(const __nv_bfloat16* __restrict__ A,
                                                    const __nv_bfloat16* __restrict__ BT,
                                                    __nv_bfloat16* __restrict__ C,
                                                    int M, int N, int K) {
    extern __shared__ __nv_bfloat16 smem[];
    const int tid   = threadIdx.x;
    const int wid   = tid >> 5;
    const int lane  = tid & 31;
    const int g     = lane >> 2;
    const int t     = lane & 3;
    const int warpM = wid & 1;
    const int warpN = wid >> 1;
    const int rowBase = blockIdx.y * BM;
    const int colBase = blockIdx.x * BN;

    float acc[4][4][4];
    #pragma unroll
    for (int i = 0; i < 4; i++)
        #pragma unroll
        for (int j = 0; j < 4; j++)
            #pragma unroll
            for (int k = 0; k < 4; k++) acc[i][j][k] = 0.0f;

    uint32_t smemBase = (uint32_t)__cvta_generic_to_shared(smem);
    const int T = K / BK;

    const int laneRow  = lane & 15;
    const int laneHalf = lane >> 4;
    const uint32_t aOff = ((warpM * 64 + laneRow) * TS + laneHalf * 8) * 2;
    const uint32_t bOff = (uint32_t)A_ELE * 2 + ((warpN * 32 + laneRow) * TS + laneHalf * 8) * 2;

    auto load_tiles = [&](int it, int stage) {
        int k0 = it * BK;
        uint32_t sA = smemBase + stage * STAGE_BYTES;
        uint32_t sB = sA + A_ELE * 2;
        #pragma unroll
        for (int j = 0; j < 2; j++) {
            int idx = tid + j * 256;
            int m   = idx >> 2;
            int c8  = (idx & 3) * 8;
            int gr  = rowBase + m;
            const __nv_bfloat16* src = A + (size_t)(gr < M ? gr : 0) * K + k0 + c8;
            cpAsync16(sA + (m * TS + c8) * 2, src, (gr < M) ? 16 : 0);
        }
        #pragma unroll
        for (int j = 0; j < 2; j++) {
            int idx = tid + j * 256;
            int n   = idx >> 2;
            int c8  = (idx & 3) * 8;
            const __nv_bfloat16* src = BT + (size_t)(colBase + n) * K + k0 + c8;
            cpAsync16(sB + (n * TS + c8) * 2, src, 16);
        }
    };

    #pragma unroll
    for (int s = 0; s < 3; s++) {
        if (s < T) load_tiles(s, s);
        cpCommit();
    }

    for (int it = 0; it < T; ++it) {
        cpWait<2>();
        __syncthreads();
        if (it + 3 < T) load_tiles(it + 3, (it + 3) & (NSTAGE - 1));
        cpCommit();

        uint32_t sStage = smemBase + (it & (NSTAGE - 1)) * STAGE_BYTES;

        #pragma unroll
        for (int ks = 0; ks < 2; ks++) {
            uint32_t af[4][4], bf[4][2];
            #pragma unroll
            for (int mt = 0; mt < 4; mt++)
                ldsmX4(af[mt][0], af[mt][1], af[mt][2], af[mt][3],
                       sStage + aOff + (mt * 16 * TS + ks * 16) * 2);
            #pragma unroll
            for (int nt2 = 0; nt2 < 2; nt2++)
                ldsmX4(bf[2 * nt2][0], bf[2 * nt2 + 1][0], bf[2 * nt2][1], bf[2 * nt2 + 1][1],
                       sStage + bOff + (nt2 * 16 * TS + ks * 16) * 2);
            #pragma unroll
            for (int mt = 0; mt < 4; mt++)
                #pragma unroll
                for (int nt = 0; nt < 4; nt++) {
                    float* d = acc[mt][nt];
                    asm volatile(
                        "mma.sync.aligned.m16n8k16.row.col.f32.bf16.bf16.f32 "
                        "{%0,%1,%2,%3}, {%4,%5,%6,%7}, {%8,%9}, {%0,%1,%2,%3};"
                        : "+f"(d[0]), "+f"(d[1]), "+f"(d[2]), "+f"(d[3])
                        : "r"(af[mt][0]), "r"(af[mt][1]), "r"(af[mt][2]), "r"(af[mt][3]),
                          "r"(bf[nt][0]), "r"(bf[nt][1]));
                }
        }
    }

    #pragma unroll
    for (int mt = 0; mt < 4; mt++) {
        int r0 = rowBase + warpM * 64 + mt * 16 + g;
        #pragma unroll
        for (int nt = 0; nt < 4; nt++) {
            int c = colBase + warpN * 32 + nt * 8 + 2 * t;
            if (r0 < M)
                *(__nv_bfloat162*)&C[(size_t)r0 * N + c] =
                    __floats2bfloat162_rn(acc[mt][nt][0], acc[mt][nt][1]);
            if (r0 + 8 < M)
                *(__nv_bfloat162*)&C[(size_t)(r0 + 8) * N + c] =
                    __floats2bfloat162_rn(acc[mt][nt][2], acc[mt][nt][3]);
        }
    }
}

// ---------------- attention scores a_s/a_d (bf16 h) --------------------------
__global__ void attn_scores(const __nv_bfloat16* __restrict__ h,
                            const float* __restrict__ att_s,
                            const float* __restrict__ att_d) {
    int n = blockIdx.x * (blockDim.x / 32) + (threadIdx.x >> 5);
    int lane = threadIdx.x & 31;
    if (n >= N_NODES) return;
    const __nv_bfloat16* hrow = h + (size_t)n * D1;
    for (int hd = 0; hd < HEADS; hd++) {
        float v = __bfloat162float(hrow[hd * 32 + lane]);
        float s = v * att_s[hd * 32 + lane];
        float d = v * att_d[hd * 32 + lane];
        #pragma unroll
        for (int o = 16; o; o >>= 1) {
            s += __shfl_down_sync(0xffffffffu, s, o);
            d += __shfl_down_sync(0xffffffffu, d, o);
        }
        if (lane == 0) {
            g_as[n * HEADS + hd] = s;
            g_ad[n * HEADS + hd] = d;
        }
    }
}

// ---------------- fused per-dst softmax + aggregate core ---------------------
// Block = one dst node, 128 threads. acc[14] covers 1792 channels as 7 bf16x2
// pairs per thread: channels (2t + 256j, +1).
struct AggSmem {
    float ad[HEADS];
    float m[HEADS];
    float den[HEADS];
    float alpha[HEADS];
    float lane_sum[OUTD];
};

__device__ __forceinline__ void fused_agg_core(const __nv_bfloat16* __restrict__ hbf,
                                               int dst, int t, AggSmem& sm, float acc[14]) {
    const int start = g_rowptr[dst];
    const int deg   = g_rowptr[dst + 1] - start;

    if (t < HEADS) {
        sm.ad[t]  = g_ad[dst * HEADS + t];
        sm.m[t]   = __uint_as_float(0xFFFFFFFFu);   // -inf pattern for atomicMaxF
        sm.den[t] = 0.0f;
    }
    __syncthreads();

    // pass 1: per-head max over incoming edges
    for (int idx = t; idx < deg * HEADS; idx += 128) {
        int e = idx / HEADS, hd = idx - e * HEADS;
        int src = g_csr[start + e];
        float s = g_as[src * HEADS + hd] + sm.ad[hd];
        s = (s > 0.0f) ? s : 0.2f * s;
        atomicMaxF(&sm.m[hd], s);
    }
    __syncthreads();

    // pass 2: per-head denominator
    for (int idx = t; idx < deg * HEADS; idx += 128) {
        int e = idx / HEADS, hd = idx - e * HEADS;
        int src = g_csr[start + e];
        float s = g_as[src * HEADS + hd] + sm.ad[hd];
        s = (s > 0.0f) ? s : 0.2f * s;
        atomicAdd(&sm.den[hd], expf(s - sm.m[hd]));
    }
    __syncthreads();

    // pass 3: aggregate alpha * h[src]
    #pragma unroll
    for (int j = 0; j < 14; j++) acc[j] = 0.0f;
    for (int e = 0; e < deg; e++) {
        int src = g_csr[start + e];
        if (t < HEADS) {
            float s = g_as[src * HEADS + t] + sm.ad[t];
            s = (s > 0.0f) ? s : 0.2f * s;
            sm.alpha[t] = expf(s - sm.m[t]) / sm.den[t];
        }
        __syncthreads();
        const __nv_bfloat16* hs = hbf + (size_t)src * D1;
        #pragma unroll
        for (int j = 0; j < 7; j++) {
            int c = 2 * t + 256 * j;
            float a = sm.alpha[c >> 5];
            float2 f = __bfloat1622float2(*(const __nv_bfloat162*)&hs[c]);
            acc[2 * j]     += a * f.x;
            acc[2 * j + 1] += a * f.y;
        }
        __syncthreads();
    }
}

// layer 1: fused agg + bias + ELU + BN1 -> bf16
__global__ __launch_bounds__(128) void gat_layer1(const __nv_bfloat16* __restrict__ hbf,
                                                  __nv_bfloat16* __restrict__ out,
                                                  const float* __restrict__ b,
                                                  const float* __restrict__ gam,
                                                  const float* __restrict__ bet,
                                                  const float* __restrict__ mu,
                                                  const float* __restrict__ var) {
    __shared__ AggSmem sm;
    int dst = blockIdx.x, t = threadIdx.x;
    float acc[14];
    fused_agg_core(hbf, dst, t, sm, acc);

    __nv_bfloat16* orow = out + (size_t)dst * D1;
    #pragma unroll
    for (int j = 0; j < 7; j++) {
        int c = 2 * t + 256 * j;
        float r[2];
        #pragma unroll
        for (int q = 0; q < 2; q++) {
            float xx = acc[2 * j + q] + b[c + q];
            xx = (xx > 0.0f) ? xx : (expf(xx) - 1.0f);
            r[q] = (xx - mu[c + q]) * rsqrtf(var[c + q] + EPS_BN) * gam[c + q] + bet[c + q];
        }
        *(__nv_bfloat162*)&orow[c] = __floats2bfloat162_rn(r[0], r[1]);
    }
}

// layer 2: fused agg + head-mean + bias + BN2 + pool
__global__ __launch_bounds__(128) void gat_layer2(const __nv_bfloat16* __restrict__ hbf,
                                                  const int* __restrict__ batch,
                                                  const float* __restrict__ b2,
                                                  const float* __restrict__ g2,
                                                  const float* __restrict__ bt2,
                                                  const float* __restrict__ mu2,
                                                  const float* __restrict__ var2) {
    __shared__ AggSmem sm;
    int dst = blockIdx.x, t = threadIdx.x;
    float acc[14];
    fused_agg_core(hbf, dst, t, sm, acc);

    if (t < OUTD) sm.lane_sum[t] = 0.0f;
    __syncthreads();
    #pragma unroll
    for (int j = 0; j < 7; j++) {
        int c = 2 * t + 256 * j;
        atomicAdd(&sm.lane_sum[c & 31], acc[2 * j]);
        atomicAdd(&sm.lane_sum[(c + 1) & 31], acc[2 * j + 1]);
    }
    __syncthreads();
    if (t < OUTD) {
        float s = sm.lane_sum[t] * (1.0f / HEADS) + b2[t];
        s = (s - mu2[t]) * rsqrtf(var2[t] + EPS_BN) * g2[t] + bt2[t];
        int gi = batch[dst];
        atomicAdd(&g_pool[gi * OUTD + t], s);
        if (t == 0) atomicAdd(&g_cnt[gi], 1.0f);
    }
}

// ---------------- final linear ----------------------------------------------
__global__ void final_lin(const float* __restrict__ lin_w,
                          const float* __restrict__ lin_b,
                          float* __restrict__ out) {
    int i = blockIdx.x * blockDim.x + threadIdx.x;
    if (i >= N_GRAPHS * N_CLASS) return;
    int g = i / N_CLASS, c = i - g * N_CLASS;
    float cnt = fmaxf(g_cnt[g], 1.0f);
    float acc = lin_b[c];
    #pragma unroll
    for (int k = 0; k < OUTD; k++)
        acc += (g_pool[g * OUTD + k] / cnt) * lin_w[k * N_CLASS + c];
    out[i] = acc;
}

// ---------------- host orchestration ----------------------------------------
extern "C" void kernel_launch(void* const* d_in, const int* in_sizes, int n_in,
                              void* d_out, int out_size) {
    const float* x        = (const float*)d_in[0];
    const int*   ei       = (const int*)  d_in[1];
    const int*   batch    = (const int*)  d_in[2];
    const float* W1       = (const float*)d_in[3];
    const float* att_src1 = (const float*)d_in[4];
    const float* att_dst1 = (const float*)d_in[5];
    const float* b1       = (const float*)d_in[6];
    const float* bn1_g    = (const float*)d_in[7];
    const float* bn1_b    = (const float*)d_in[8];
    const float* bn1_m    = (const float*)d_in[9];
    const float* bn1_v    = (const float*)d_in[10];
    const float* W2       = (const float*)d_in[11];
    const float* att_src2 = (const float*)d_in[12];
    const float* att_dst2 = (const float*)d_in[13];
    const float* b2       = (const float*)d_in[14];
    const float* bn2_g    = (const float*)d_in[15];
    const float* bn2_b    = (const float*)d_in[16];
    const float* bn2_m    = (const float*)d_in[17];
    const float* bn2_v    = (const float*)d_in[18];
    const float* lin_w    = (const float*)d_in[19];
    const float* lin_b    = (const float*)d_in[20];
    float* out = (float*)d_out;

    float *pool_ptr, *cnt_ptr;
    int *deg_ptr, *rowptr_ptr, *next_ptr;
    __nv_bfloat16 *xbf, *w1t, *w2t, *actbf, *hbf;
    cudaGetSymbolAddress((void**)&pool_ptr,  g_pool);
    cudaGetSymbolAddress((void**)&cnt_ptr,   g_cnt);
    cudaGetSymbolAddress((void**)&deg_ptr,   g_deg);
    cudaGetSymbolAddress((void**)&rowptr_ptr,g_rowptr);
    cudaGetSymbolAddress((void**)&next_ptr,  g_next);
    cudaGetSymbolAddress((void**)&xbf,       g_xbf);
    cudaGetSymbolAddress((void**)&w1t,       g_w1t);
    cudaGetSymbolAddress((void**)&w2t,       g_w2t);
    cudaGetSymbolAddress((void**)&actbf,     g_actbf);
    cudaGetSymbolAddress((void**)&hbf,       g_hbf);

    const int SMEM_BYTES = NSTAGE * STAGE_BYTES;   // 81920 B
    cudaFuncSetAttribute(bf16_gemm, cudaFuncAttributeMaxDynamicSharedMemorySize, SMEM_BYTES);
    dim3 gemmGrid(D1 / BN, (N_NODES + BM - 1) / BM);

    // ===== conversions + CSR build + init =====
    cvt_bf16<<<(N_NODES * N_FEAT / 4 + 255) / 256, 256>>>(x, xbf, N_NODES * N_FEAT / 4);
    transpose_cvt<<<dim3(D1 / 32, N_FEAT / 32), dim3(32, 8)>>>(W1, w1t, N_FEAT, D1);
    transpose_cvt<<<dim3(D1 / 32, D1 / 32), dim3(32, 8)>>>(W2, w2t, D1, D1);
    cudaMemsetAsync(deg_ptr, 0, (size_t)N_NODES * 4);
    cudaMemsetAsync(pool_ptr, 0, (size_t)N_GRAPHS * OUTD * 4);
    cudaMemsetAsync(cnt_ptr,  0, (size_t)N_GRAPHS * 4);
    count_deg<<<(E_TOT + 255) / 256, 256>>>(ei);
    scan_rowptr<<<1, 256>>>();
    cudaMemcpyAsync(next_ptr, rowptr_ptr, (size_t)N_NODES * 4, cudaMemcpyDeviceToDevice);
    scatter_csr<<<(E_TOT + 255) / 256, 256>>>(ei);

    // ===== layer 1 =====
    bf16_gemm<<<gemmGrid, 256, SMEM_BYTES>>>(xbf, w1t, hbf, N_NODES, D1, N_FEAT);   // h1
    attn_scores<<<(N_NODES + 7) / 8, 256>>>(hbf, att_src1, att_dst1);
    gat_layer1<<<N_NODES, 128>>>(hbf, actbf, b1, bn1_g, bn1_b, bn1_m, bn1_v);

    // ===== layer 2 =====
    bf16_gemm<<<gemmGrid, 256, SMEM_BYTES>>>(actbf, w2t, hbf, N_NODES, D1, D1);     // h2
    attn_scores<<<(N_NODES + 7) / 8, 256>>>(hbf, att_src2, att_dst2);
    gat_layer2<<<N_NODES, 128>>>(hbf, batch, b2, bn2_g, bn2_b, bn2_m, bn2_v);

    // ===== final linear =====
    final_lin<<<1, 128>>>(lin_w, lin_b, out);
}